// round 10
// baseline (speedup 1.0000x reference)
#include <cuda_runtime.h>
#include <cuda_fp16.h>
#include <cstdint>

#define NN 100000
#define EE 1600000
#define BG 64
#define HD 128
#define DIN 9
#define EPS 1e-5f
#define NB_SCAN 391      // ceil(NN/256)
#define EMB_BLOCKS 3125  // 32 nodes per block
#define CD_BLOCKS 6250   // count_deg blocks

// ---------------- scratch (static __device__, no allocation) ----------------
__device__ __half g_h[2][NN * HD];       // ping-pong node features (fp16)
__device__ int    g_deg[NN];
__device__ int    g_rowptr[NN];
__device__ int    g_cursor[NN];
__device__ int    g_col[EE];
__device__ int    g_bsum[512];
__device__ float  g_cnt[BG];

// ---------------- fp16 helpers ----------------
__device__ __forceinline__ uint32_t pack2h(float a, float b) {
    __half2 t = __floats2half2_rn(a, b);
    return *(uint32_t*)&t;
}
__device__ __forceinline__ void split2h(float x, float& hi, float& lo) {
    hi = __half2float(__float2half_rn(x));
    lo = x - hi;
}
__device__ __forceinline__ void mma_f16(float* c, uint32_t a0, uint32_t a1,
                                        uint32_t a2, uint32_t a3,
                                        uint32_t b0, uint32_t b1) {
    asm volatile(
        "mma.sync.aligned.m16n8k16.row.col.f32.f16.f16.f32 "
        "{%0,%1,%2,%3},{%4,%5,%6,%7},{%8,%9},{%0,%1,%2,%3};\n"
        : "+f"(c[0]), "+f"(c[1]), "+f"(c[2]), "+f"(c[3])
        : "r"(a0), "r"(a1), "r"(a2), "r"(a3), "r"(b0), "r"(b1));
}

// ---------------- init zeroing (deg, cnt, graph-pool out) ----------------
__global__ void zero_misc(float* __restrict__ gr) {
    int i = blockIdx.x * blockDim.x + threadIdx.x;
    if (i < NN) g_deg[i] = 0;
    if (i < BG * 2 * HD) gr[i] = 0.f;
    if (i < BG) g_cnt[i] = 0.f;
}

// ---------------- fat start: embed || count_deg || count_batch ----------------
__global__ void __launch_bounds__(256) fat_start(
    const float* __restrict__ x, const float* __restrict__ W0,
    const float* __restrict__ b0, const float* __restrict__ g0,
    const float* __restrict__ be0,
    const int* __restrict__ dst, const int* __restrict__ batch) {
    int bid = blockIdx.x;
    int tid = threadIdx.x;
    if (bid < EMB_BLOCKS) {
        __shared__ float Ws[HD * DIN];
        __shared__ float bs[HD], gs[HD], es[HD];
        for (int i = tid; i < HD * DIN; i += 256) Ws[i] = W0[i];
        if (tid < HD) { bs[tid] = b0[tid]; gs[tid] = g0[tid]; es[tid] = be0[tid]; }
        __syncthreads();
        int warp = tid >> 5;
        int lane = tid & 31;
        __half* hout = g_h[0];
#pragma unroll
        for (int it = 0; it < 4; it++) {
            int n = bid * 32 + it * 8 + warp;   // always < NN (3125*32 == NN)
            float xv = (lane < DIN) ? x[n * DIN + lane] : 0.f;
            float xj[DIN];
#pragma unroll
            for (int j = 0; j < DIN; j++) xj[j] = __shfl_sync(0xffffffffu, xv, j);
            float val[4];
#pragma unroll
            for (int q = 0; q < 4; q++) {
                int f = lane * 4 + q;
                float v = bs[f];
#pragma unroll
                for (int j = 0; j < DIN; j++) v += xj[j] * Ws[f * DIN + j];
                val[q] = v;
            }
            float s = val[0] + val[1] + val[2] + val[3];
            float s2 = val[0]*val[0] + val[1]*val[1] + val[2]*val[2] + val[3]*val[3];
#pragma unroll
            for (int o = 16; o; o >>= 1) {
                s += __shfl_xor_sync(0xffffffffu, s, o);
                s2 += __shfl_xor_sync(0xffffffffu, s2, o);
            }
            float mean = s * (1.f / HD);
            float var = s2 * (1.f / HD) - mean * mean;
            float rstd = rsqrtf(var + EPS);
            uint2 w;
            {
                int f = lane * 4;
                float o0 = fmaxf((val[0] - mean) * rstd * gs[f] + es[f], 0.f);
                float o1 = fmaxf((val[1] - mean) * rstd * gs[f+1] + es[f+1], 0.f);
                float o2 = fmaxf((val[2] - mean) * rstd * gs[f+2] + es[f+2], 0.f);
                float o3 = fmaxf((val[3] - mean) * rstd * gs[f+3] + es[f+3], 0.f);
                w.x = pack2h(o0, o1);
                w.y = pack2h(o2, o3);
            }
            *(uint2*)(hout + n * HD + lane * 4) = w;
        }
    } else if (bid < EMB_BLOCKS + CD_BLOCKS) {
        int e = (bid - EMB_BLOCKS) * 256 + tid;
        if (e < EE) atomicAdd(&g_deg[dst[e]], 1);
    } else {
        int i = (bid - EMB_BLOCKS - CD_BLOCKS) * 256 + tid;
        if (i < NN) atomicAdd(&g_cnt[batch[i]], 1.f);
    }
}

// ---------------- CSR scans + fill ----------------
__global__ void scan1() {
    __shared__ int sm[256];
    int t = threadIdx.x;
    int i = blockIdx.x * 256 + t;
    sm[t] = (i < NN) ? g_deg[i] : 0;
    __syncthreads();
#pragma unroll
    for (int o = 128; o; o >>= 1) {
        if (t < o) sm[t] += sm[t + o];
        __syncthreads();
    }
    if (t == 0) g_bsum[blockIdx.x] = sm[0];
}
// scan3 computes its own block offset by reducing g_bsum[0..bid-1]
__global__ void scan3() {
    __shared__ int sm[256];
    __shared__ int offsh;
    int t = threadIdx.x;
    // block offset = sum of previous block sums
    int partial = 0;
    for (int i = t; i < blockIdx.x; i += 256) partial += g_bsum[i];
#pragma unroll
    for (int o = 16; o; o >>= 1) partial += __shfl_xor_sync(0xffffffffu, partial, o);
    if ((t & 31) == 0) sm[t >> 5] = partial;
    __syncthreads();
    if (t == 0) {
        int s = 0;
#pragma unroll
        for (int w = 0; w < 8; w++) s += sm[w];
        offsh = s;
    }
    __syncthreads();
    int boff = offsh;
    __syncthreads();
    int i = blockIdx.x * 256 + t;
    int v = (i < NN) ? g_deg[i] : 0;
    sm[t] = v;
    __syncthreads();
    for (int o = 1; o < 256; o <<= 1) {
        int add = (t >= o) ? sm[t - o] : 0;
        __syncthreads();
        sm[t] += add;
        __syncthreads();
    }
    if (i < NN) {
        int excl = sm[t] - v + boff;
        g_rowptr[i] = excl;
        g_cursor[i] = excl;
    }
}
__global__ void fill_csr(const int* __restrict__ src, const int* __restrict__ dst) {
    int e = blockIdx.x * blockDim.x + threadIdx.x;
    if (e < EE) {
        int p = atomicAdd(&g_cursor[dst[e]], 1);
        g_col[p] = src[e];
    }
}

// ---------------- fused SAGE layer: gather-mean + GEMM + bias + LN + ReLU ------
// Block 128 rows x 128 cols, 8 warps as 4x2 (warptile 32x64).
// Phase 1: each warp mean-aggregates 16 of the block's nodes (2 at a time,
//          16 lanes/node, uint4 fp16 gathers), splits fp32 sum into fp16
//          hi/lo, stores to AggHi/AggLo smem (stride 68 words, conflict-free).
// Phase 2: K=256 mainloop. kc 0..3: A frags read directly from AggHi/AggLo
//          (3 mma terms). kc 4..7: A = block's own g_h rows staged via regs
//          (fp16 exact, 2 terms). B = Wl/Wr split, staged per chunk, pipelined.
#define KPW 20   // words per row per 32-k staging chunk
#define AST 68   // words per row of Agg arrays (64 data + 4 pad)

#define SM_AGGHI 0
#define SM_AGGLO (128 * AST)
#define SM_ASH   (2 * 128 * AST)
#define SM_BSHI  (SM_ASH + 128 * KPW)
#define SM_BSLO  (SM_BSHI + 128 * KPW)
#define SM_MISC  (SM_BSLO + 128 * KPW)          // bias/gamma/beta/red (floats)
#define SM_WORDS (SM_MISC + 128 * 3 + 512)

__device__ __forceinline__ void acc8(float* acc, uint4 v) {
    float2 t;
    t = __half22float2(*(__half2*)&v.x); acc[0] += t.x; acc[1] += t.y;
    t = __half22float2(*(__half2*)&v.y); acc[2] += t.x; acc[3] += t.y;
    t = __half22float2(*(__half2*)&v.z); acc[4] += t.x; acc[5] += t.y;
    t = __half22float2(*(__half2*)&v.w); acc[6] += t.x; acc[7] += t.y;
}

__global__ void __launch_bounds__(256) sage_layer(
    int ibuf,
    const float* __restrict__ Wl, const float* __restrict__ Wr,
    const float* __restrict__ bias, const float* __restrict__ gamma,
    const float* __restrict__ beta,
    int obuf, float* __restrict__ ext_out) {
    extern __shared__ uint32_t smw[];
    uint32_t* AggHi = smw + SM_AGGHI;
    uint32_t* AggLo = smw + SM_AGGLO;
    uint32_t* AsH   = smw + SM_ASH;
    uint32_t* BsHi  = smw + SM_BSHI;
    uint32_t* BsLo  = smw + SM_BSLO;
    float* bias_s  = (float*)(smw + SM_MISC);
    float* gamma_s = bias_s + 128;
    float* beta_s  = gamma_s + 128;
    float* red     = beta_s + 128;

    __half* __restrict__ out_h = g_h[obuf];
    const __half* __restrict__ Hp = g_h[ibuf];

    int tid = threadIdx.x;
    int lane = tid & 31;
    int warp = tid >> 5;
    int g = lane >> 2;
    int t = lane & 3;
    int wrow = (warp >> 1) * 32;
    int wcol = (warp & 1) * 64;
    int brow = blockIdx.x * 128;

    if (tid < 128) {
        bias_s[tid] = bias[tid];
        gamma_s[tid] = gamma[tid];
        beta_s[tid] = beta[tid];
    }

    // staging coords for B / A-h
    int arow = tid >> 3, akq = tid & 7;

    // prefetch B chunk 0 (Wl) early — independent of gather
    float4 pb[4];
#pragma unroll
    for (int it = 0; it < 4; it++)
        pb[it] = *(const float4*)(Wl + (arow + it * 32) * HD + akq * 4);

    // ---- Phase 1: aggregate this block's 128 nodes into AggHi/AggLo ----
    {
        int sub = lane >> 4;        // 2 nodes per warp in flight
        int l16 = lane & 15;
#pragma unroll 1
        for (int i = 0; i < 8; i++) {
            int nl = warp * 16 + i * 2 + sub;
            int node = brow + nl;
            float acc[8] = {0.f, 0.f, 0.f, 0.f, 0.f, 0.f, 0.f, 0.f};
            int d = 0;
            if (node < NN) {
                int start = g_rowptr[node];
                d = g_deg[node];
                int j = 0;
                for (; j + 3 < d; j += 4) {
                    int s0 = g_col[start + j];
                    int s1 = g_col[start + j + 1];
                    int s2 = g_col[start + j + 2];
                    int s3 = g_col[start + j + 3];
                    uint4 v0 = *(const uint4*)(Hp + s0 * HD + l16 * 8);
                    uint4 v1 = *(const uint4*)(Hp + s1 * HD + l16 * 8);
                    uint4 v2 = *(const uint4*)(Hp + s2 * HD + l16 * 8);
                    uint4 v3 = *(const uint4*)(Hp + s3 * HD + l16 * 8);
                    acc8(acc, v0); acc8(acc, v1); acc8(acc, v2); acc8(acc, v3);
                }
                for (; j < d; j++) {
                    int s = g_col[start + j];
                    uint4 v = *(const uint4*)(Hp + s * HD + l16 * 8);
                    acc8(acc, v);
                }
            }
            float inv = 1.f / (float)max(d, 1);
            uint4 whi, wlo;
            {
                float h0, l0, h1, l1;
                split2h(acc[0] * inv, h0, l0); split2h(acc[1] * inv, h1, l1);
                whi.x = pack2h(h0, h1); wlo.x = pack2h(l0, l1);
                split2h(acc[2] * inv, h0, l0); split2h(acc[3] * inv, h1, l1);
                whi.y = pack2h(h0, h1); wlo.y = pack2h(l0, l1);
                split2h(acc[4] * inv, h0, l0); split2h(acc[5] * inv, h1, l1);
                whi.z = pack2h(h0, h1); wlo.z = pack2h(l0, l1);
                split2h(acc[6] * inv, h0, l0); split2h(acc[7] * inv, h1, l1);
                whi.w = pack2h(h0, h1); wlo.w = pack2h(l0, l1);
            }
            *(uint4*)&AggHi[nl * AST + l16 * 4] = whi;
            *(uint4*)&AggLo[nl * AST + l16 * 4] = wlo;
        }
    }
    __syncthreads();

    // ---- Phase 2: mainloop ----
    float acc[2][8][4];
#pragma unroll
    for (int mi = 0; mi < 2; mi++)
#pragma unroll
        for (int ni = 0; ni < 8; ni++)
#pragma unroll
            for (int c = 0; c < 4; c++) acc[mi][ni][c] = 0.f;

    uint2 pah[4];   // prefetched A (h half, fp16)
    int agrow = brow + arow;

    for (int kc = 0; kc < 8; kc++) {
        const bool isagg = (kc < 4);
        if (kc > 0) __syncthreads();   // previous chunk's mma done with Bs/AsH
        // ---- store prefetched regs -> smem ----
        if (!isagg) {
#pragma unroll
            for (int it = 0; it < 4; it++) {
                int o = (arow + it * 32) * KPW + akq * 2;
                AsH[o]     = pah[it].x;
                AsH[o + 1] = pah[it].y;
            }
        }
#pragma unroll
        for (int it = 0; it < 4; it++) {
            float4 v = pb[it];
            float hx, lx, hy, ly, hz, lz, hw, lw;
            split2h(v.x, hx, lx); split2h(v.y, hy, ly);
            split2h(v.z, hz, lz); split2h(v.w, hw, lw);
            int o = (arow + it * 32) * KPW + akq * 2;
            BsHi[o]     = pack2h(hx, hy);
            BsHi[o + 1] = pack2h(hz, hw);
            BsLo[o]     = pack2h(lx, ly);
            BsLo[o + 1] = pack2h(lz, lw);
        }
        __syncthreads();
        // ---- prefetch next chunk ----
        if (kc < 7) {
            int kn = kc + 1;
            bool nagg = (kn < 4);
            int col0 = (kn * 32) & 127;
            if (!nagg) {
#pragma unroll
                for (int it = 0; it < 4; it++) {
                    int grow = agrow + it * 32;
                    pah[it] = (grow < NN)
                                  ? *(const uint2*)(Hp + grow * HD + col0 + akq * 4)
                                  : make_uint2(0u, 0u);
                }
            }
            const float* __restrict__ Bp = nagg ? Wl : Wr;
#pragma unroll
            for (int it = 0; it < 4; it++)
                pb[it] = *(const float4*)(Bp + (arow + it * 32) * HD + col0 + akq * 4);
        }
        // ---- mma on chunk kc ----
#pragma unroll
        for (int ks = 0; ks < 2; ks++) {
            uint32_t ah[2][4], al[2][4], bh[8][2], bl[8][2];
            if (isagg) {
                int base = kc * 16 + ks * 8;
#pragma unroll
                for (int mi = 0; mi < 2; mi++) {
                    int r0 = (wrow + mi * 16 + g) * AST + base;
                    ah[mi][0] = AggHi[r0 + t];
                    ah[mi][1] = AggHi[r0 + 8 * AST + t];
                    ah[mi][2] = AggHi[r0 + t + 4];
                    ah[mi][3] = AggHi[r0 + 8 * AST + t + 4];
                    al[mi][0] = AggLo[r0 + t];
                    al[mi][1] = AggLo[r0 + 8 * AST + t];
                    al[mi][2] = AggLo[r0 + t + 4];
                    al[mi][3] = AggLo[r0 + 8 * AST + t + 4];
                }
            } else {
                int kw = ks * 8;
#pragma unroll
                for (int mi = 0; mi < 2; mi++) {
                    int r0 = (wrow + mi * 16 + g) * KPW + kw;
                    ah[mi][0] = AsH[r0 + t];
                    ah[mi][1] = AsH[r0 + 8 * KPW + t];
                    ah[mi][2] = AsH[r0 + t + 4];
                    ah[mi][3] = AsH[r0 + 8 * KPW + t + 4];
                }
            }
            {
                int kw = ks * 8;
#pragma unroll
                for (int ni = 0; ni < 8; ni++) {
                    int c0 = (wcol + ni * 8 + g) * KPW + kw;
                    bh[ni][0] = BsHi[c0 + t];
                    bh[ni][1] = BsHi[c0 + t + 4];
                    bl[ni][0] = BsLo[c0 + t];
                    bl[ni][1] = BsLo[c0 + t + 4];
                }
            }
#pragma unroll
            for (int mi = 0; mi < 2; mi++)
#pragma unroll
                for (int ni = 0; ni < 8; ni++) {
                    mma_f16(acc[mi][ni], ah[mi][0], ah[mi][1], ah[mi][2], ah[mi][3],
                            bh[ni][0], bh[ni][1]);
                    if (isagg)
                        mma_f16(acc[mi][ni], al[mi][0], al[mi][1], al[mi][2], al[mi][3],
                                bh[ni][0], bh[ni][1]);
                    mma_f16(acc[mi][ni], ah[mi][0], ah[mi][1], ah[mi][2], ah[mi][3],
                            bl[ni][0], bl[ni][1]);
                }
        }
    }
    __syncthreads();

    // ---- epilogue: bias + LN(128 cols) + ReLU ----
    float ps[2][2], pq[2][2];
#pragma unroll
    for (int mi = 0; mi < 2; mi++)
#pragma unroll
        for (int h = 0; h < 2; h++) { ps[mi][h] = 0.f; pq[mi][h] = 0.f; }
#pragma unroll
    for (int mi = 0; mi < 2; mi++)
#pragma unroll
        for (int ni = 0; ni < 8; ni++) {
            int cbase = wcol + ni * 8 + 2 * t;
            float b0v = bias_s[cbase], b1v = bias_s[cbase + 1];
            float v;
            v = acc[mi][ni][0] + b0v; acc[mi][ni][0] = v; ps[mi][0] += v; pq[mi][0] += v * v;
            v = acc[mi][ni][1] + b1v; acc[mi][ni][1] = v; ps[mi][0] += v; pq[mi][0] += v * v;
            v = acc[mi][ni][2] + b0v; acc[mi][ni][2] = v; ps[mi][1] += v; pq[mi][1] += v * v;
            v = acc[mi][ni][3] + b1v; acc[mi][ni][3] = v; ps[mi][1] += v; pq[mi][1] += v * v;
        }
#pragma unroll
    for (int mi = 0; mi < 2; mi++)
#pragma unroll
        for (int h = 0; h < 2; h++) {
#pragma unroll
            for (int o = 1; o < 4; o <<= 1) {
                ps[mi][h] += __shfl_xor_sync(0xffffffffu, ps[mi][h], o);
                pq[mi][h] += __shfl_xor_sync(0xffffffffu, pq[mi][h], o);
            }
        }
    if (t == 0) {
#pragma unroll
        for (int mi = 0; mi < 2; mi++)
#pragma unroll
            for (int h = 0; h < 2; h++) {
                int rl = wrow + mi * 16 + h * 8 + g;
                red[rl * 4 + (warp & 1) * 2 + 0] = ps[mi][h];
                red[rl * 4 + (warp & 1) * 2 + 1] = pq[mi][h];
            }
    }
    __syncthreads();
#pragma unroll
    for (int mi = 0; mi < 2; mi++)
#pragma unroll
        for (int h = 0; h < 2; h++) {
            int rl = wrow + mi * 16 + h * 8 + g;
            float S = red[rl * 4 + 0] + red[rl * 4 + 2];
            float Q = red[rl * 4 + 1] + red[rl * 4 + 3];
            float mean = S * (1.f / HD);
            float var = Q * (1.f / HD) - mean * mean;
            float rstd = rsqrtf(var + EPS);
            int grow = brow + rl;
            if (grow < NN) {
#pragma unroll
                for (int ni = 0; ni < 8; ni++) {
                    int cbase = wcol + ni * 8 + 2 * t;
                    float v0 = acc[mi][ni][h * 2 + 0];
                    float v1 = acc[mi][ni][h * 2 + 1];
                    float o0 = fmaxf((v0 - mean) * rstd * gamma_s[cbase] + beta_s[cbase], 0.f);
                    float o1 = fmaxf((v1 - mean) * rstd * gamma_s[cbase + 1] + beta_s[cbase + 1], 0.f);
                    if (ext_out) {
                        *(float2*)(ext_out + grow * HD + cbase) = make_float2(o0, o1);
                    } else {
                        *(uint32_t*)(out_h + grow * HD + cbase) = pack2h(o0, o1);
                    }
                }
            }
        }
}

// ---------------- pooling ----------------
__global__ void pool_accum(const float* __restrict__ ne, const int* __restrict__ batch,
                           float* __restrict__ gout) {
    int tx = threadIdx.x;  // 128 = column
    int n0 = blockIdx.x * 128;
    int n1 = min(n0 + 128, NN);
    if (n0 >= NN) return;
    int cur = batch[n0];
    float sum = 0.f, mx = 0.f;
    for (int n = n0; n < n1; n++) {
        int b = batch[n];
        float v = ne[n * HD + tx];
        if (b != cur) {
            atomicAdd(&gout[cur * 256 + tx], sum);
            atomicMax((int*)&gout[cur * 256 + HD + tx], __float_as_int(mx));
            sum = 0.f; mx = 0.f; cur = b;
        }
        sum += v;
        mx = fmaxf(mx, v);
    }
    atomicAdd(&gout[cur * 256 + tx], sum);
    atomicMax((int*)&gout[cur * 256 + HD + tx], __float_as_int(mx));
}
__global__ void finalize_pool(float* __restrict__ gout) {
    int b = blockIdx.x;
    int tx = threadIdx.x;
    gout[b * 256 + tx] /= fmaxf(g_cnt[b], 1.f);
}

// ---------------- launch ----------------
extern "C" void kernel_launch(void* const* d_in, const int* in_sizes, int n_in,
                              void* d_out, int out_size) {
    const float* x   = (const float*)d_in[0];
    const int* ei    = (const int*)d_in[1];
    const int* batch = (const int*)d_in[2];
    const float* W0  = (const float*)d_in[3];
    const float* b0  = (const float*)d_in[4];
    const float* g0  = (const float*)d_in[5];
    const float* be0 = (const float*)d_in[6];
    const float* Wl1 = (const float*)d_in[7];
    const float* bl1 = (const float*)d_in[8];
    const float* Wr1 = (const float*)d_in[9];
    const float* g1  = (const float*)d_in[10];
    const float* be1 = (const float*)d_in[11];
    const float* Wl2 = (const float*)d_in[12];
    const float* bl2 = (const float*)d_in[13];
    const float* Wr2 = (const float*)d_in[14];
    const float* g2  = (const float*)d_in[15];
    const float* be2 = (const float*)d_in[16];
    const float* Wl3 = (const float*)d_in[17];
    const float* bl3 = (const float*)d_in[18];
    const float* Wr3 = (const float*)d_in[19];
    const float* g3  = (const float*)d_in[20];
    const float* be3 = (const float*)d_in[21];

    float* out = (float*)d_out;
    float* ne = out;                           // node_embed (N*H)
    float* gr = out + (size_t)NN * HD;         // graph_embed (B*2H)

    const int* src = ei;
    const int* dst = ei + EE;

    size_t smemSz = (size_t)SM_WORDS * 4;
    cudaFuncSetAttribute(sage_layer, cudaFuncAttributeMaxDynamicSharedMemorySize,
                         (int)smemSz);

    zero_misc<<<NB_SCAN, 256>>>(gr);
    fat_start<<<EMB_BLOCKS + CD_BLOCKS + NB_SCAN, 256>>>(x, W0, b0, g0, be0, dst, batch);
    scan1<<<NB_SCAN, 256>>>();
    scan3<<<NB_SCAN, 256>>>();
    fill_csr<<<(EE + 255) / 256, 256>>>(src, dst);

    int gemm_blocks = (NN + 127) / 128;

    // layer 1: h0 -> h1
    sage_layer<<<gemm_blocks, 256, smemSz>>>(0, Wl1, Wr1, bl1, g1, be1, 1, nullptr);
    // layer 2: h1 -> h0
    sage_layer<<<gemm_blocks, 256, smemSz>>>(1, Wl2, Wr2, bl2, g2, be2, 0, nullptr);
    // layer 3: h0 -> d_out node region (fp32)
    sage_layer<<<gemm_blocks, 256, smemSz>>>(0, Wl3, Wr3, bl3, g3, be3, 0, ne);

    pool_accum<<<(NN + 127) / 128, 128>>>(ne, batch, gr);
    finalize_pool<<<BG, 128>>>(gr);
}

// round 11
// speedup vs baseline: 1.2980x; 1.2980x over previous
#include <cuda_runtime.h>
#include <cuda_fp16.h>
#include <cstdint>

#define NN 100000
#define EE 1600000
#define BG 64
#define HD 128
#define DIN 9
#define EPS 1e-5f
#define NB_SCAN 391      // ceil(NN/256)
#define EMB_BLOCKS 3125  // 32 nodes per block
#define CD_BLOCKS 6250   // count_deg blocks

// ---------------- scratch (static __device__, no allocation) ----------------
__device__ __half g_h[2][NN * HD];       // ping-pong node features (fp16)
__device__ __half g_aggh[NN * HD];       // aggregated mean, fp16 hi part
__device__ __half g_aggl[NN * HD];       // aggregated mean, fp16 lo part
__device__ __half g_Whi[3][2 * HD * HD]; // pre-split weights hi: [layer][Wl;Wr][c][k]
__device__ __half g_Wlo[3][2 * HD * HD]; // pre-split weights lo
__device__ int    g_deg[NN];
__device__ int    g_rowptr[NN];
__device__ int    g_cursor[NN];
__device__ int    g_col[EE];
__device__ int    g_bsum[512];
__device__ float  g_cnt[BG];

// ---------------- fp16 helpers ----------------
__device__ __forceinline__ uint32_t pack2h(float a, float b) {
    __half2 t = __floats2half2_rn(a, b);
    return *(uint32_t*)&t;
}
__device__ __forceinline__ void split2h(float x, float& hi, float& lo) {
    hi = __half2float(__float2half_rn(x));
    lo = x - hi;
}
__device__ __forceinline__ void mma_f16(float* c, uint32_t a0, uint32_t a1,
                                        uint32_t a2, uint32_t a3,
                                        uint32_t b0, uint32_t b1) {
    asm volatile(
        "mma.sync.aligned.m16n8k16.row.col.f32.f16.f16.f32 "
        "{%0,%1,%2,%3},{%4,%5,%6,%7},{%8,%9},{%0,%1,%2,%3};\n"
        : "+f"(c[0]), "+f"(c[1]), "+f"(c[2]), "+f"(c[3])
        : "r"(a0), "r"(a1), "r"(a2), "r"(a3), "r"(b0), "r"(b1));
}

// ---------------- weight pre-split: fp32 -> (hi, lo) fp16, native [c][k] layout ----
__global__ void split_w(const float* __restrict__ Wl1, const float* __restrict__ Wr1,
                        const float* __restrict__ Wl2, const float* __restrict__ Wr2,
                        const float* __restrict__ Wl3, const float* __restrict__ Wr3) {
    int idx = blockIdx.x * 256 + threadIdx.x;       // 0 .. 3*32768-1
    if (idx >= 3 * 2 * HD * HD) return;
    int l = idx >> 15;
    int rem = idx & 32767;                           // part*16384 + i
    int part = rem >> 14;
    int i = rem & 16383;
    const float* W;
    if (l == 0) W = part ? Wr1 : Wl1;
    else if (l == 1) W = part ? Wr2 : Wl2;
    else W = part ? Wr3 : Wl3;
    float hi, lo;
    split2h(W[i], hi, lo);
    g_Whi[l][rem] = __float2half_rn(hi);
    g_Wlo[l][rem] = __float2half_rn(lo);
}

// ---------------- init zeroing (deg, cnt, graph-pool out) ----------------
__global__ void zero_misc(float* __restrict__ gr) {
    int i = blockIdx.x * blockDim.x + threadIdx.x;
    if (i < NN) g_deg[i] = 0;
    if (i < BG * 2 * HD) gr[i] = 0.f;
    if (i < BG) g_cnt[i] = 0.f;
}

// ---------------- fat start: embed || count_deg || count_batch ----------------
__global__ void __launch_bounds__(256) fat_start(
    const float* __restrict__ x, const float* __restrict__ W0,
    const float* __restrict__ b0, const float* __restrict__ g0,
    const float* __restrict__ be0,
    const int* __restrict__ dst, const int* __restrict__ batch) {
    int bid = blockIdx.x;
    int tid = threadIdx.x;
    if (bid < EMB_BLOCKS) {
        __shared__ float Ws[HD * DIN];
        __shared__ float bs[HD], gs[HD], es[HD];
        for (int i = tid; i < HD * DIN; i += 256) Ws[i] = W0[i];
        if (tid < HD) { bs[tid] = b0[tid]; gs[tid] = g0[tid]; es[tid] = be0[tid]; }
        __syncthreads();
        int warp = tid >> 5;
        int lane = tid & 31;
        __half* hout = g_h[0];
#pragma unroll
        for (int it = 0; it < 4; it++) {
            int n = bid * 32 + it * 8 + warp;   // always < NN (3125*32 == NN)
            float xv = (lane < DIN) ? x[n * DIN + lane] : 0.f;
            float xj[DIN];
#pragma unroll
            for (int j = 0; j < DIN; j++) xj[j] = __shfl_sync(0xffffffffu, xv, j);
            float val[4];
#pragma unroll
            for (int q = 0; q < 4; q++) {
                int f = lane * 4 + q;
                float v = bs[f];
#pragma unroll
                for (int j = 0; j < DIN; j++) v += xj[j] * Ws[f * DIN + j];
                val[q] = v;
            }
            float s = val[0] + val[1] + val[2] + val[3];
            float s2 = val[0]*val[0] + val[1]*val[1] + val[2]*val[2] + val[3]*val[3];
#pragma unroll
            for (int o = 16; o; o >>= 1) {
                s += __shfl_xor_sync(0xffffffffu, s, o);
                s2 += __shfl_xor_sync(0xffffffffu, s2, o);
            }
            float mean = s * (1.f / HD);
            float var = s2 * (1.f / HD) - mean * mean;
            float rstd = rsqrtf(var + EPS);
            uint2 w;
            {
                int f = lane * 4;
                float o0 = fmaxf((val[0] - mean) * rstd * gs[f] + es[f], 0.f);
                float o1 = fmaxf((val[1] - mean) * rstd * gs[f+1] + es[f+1], 0.f);
                float o2 = fmaxf((val[2] - mean) * rstd * gs[f+2] + es[f+2], 0.f);
                float o3 = fmaxf((val[3] - mean) * rstd * gs[f+3] + es[f+3], 0.f);
                w.x = pack2h(o0, o1);
                w.y = pack2h(o2, o3);
            }
            *(uint2*)(hout + n * HD + lane * 4) = w;
        }
    } else if (bid < EMB_BLOCKS + CD_BLOCKS) {
        int e = (bid - EMB_BLOCKS) * 256 + tid;
        if (e < EE) atomicAdd(&g_deg[dst[e]], 1);
    } else {
        int i = (bid - EMB_BLOCKS - CD_BLOCKS) * 256 + tid;
        if (i < NN) atomicAdd(&g_cnt[batch[i]], 1.f);
    }
}

// ---------------- CSR scans + fill ----------------
__global__ void scan1() {
    __shared__ int sm[256];
    int t = threadIdx.x;
    int i = blockIdx.x * 256 + t;
    sm[t] = (i < NN) ? g_deg[i] : 0;
    __syncthreads();
#pragma unroll
    for (int o = 128; o; o >>= 1) {
        if (t < o) sm[t] += sm[t + o];
        __syncthreads();
    }
    if (t == 0) g_bsum[blockIdx.x] = sm[0];
}
// scan3 computes its own block offset by reducing g_bsum[0..bid-1]
__global__ void scan3() {
    __shared__ int sm[256];
    __shared__ int offsh;
    int t = threadIdx.x;
    int partial = 0;
    for (int i = t; i < blockIdx.x; i += 256) partial += g_bsum[i];
#pragma unroll
    for (int o = 16; o; o >>= 1) partial += __shfl_xor_sync(0xffffffffu, partial, o);
    if ((t & 31) == 0) sm[t >> 5] = partial;
    __syncthreads();
    if (t == 0) {
        int s = 0;
#pragma unroll
        for (int w = 0; w < 8; w++) s += sm[w];
        offsh = s;
    }
    __syncthreads();
    int boff = offsh;
    __syncthreads();
    int i = blockIdx.x * 256 + t;
    int v = (i < NN) ? g_deg[i] : 0;
    sm[t] = v;
    __syncthreads();
    for (int o = 1; o < 256; o <<= 1) {
        int add = (t >= o) ? sm[t - o] : 0;
        __syncthreads();
        sm[t] += add;
        __syncthreads();
    }
    if (i < NN) {
        int excl = sm[t] - v + boff;
        g_rowptr[i] = excl;
        g_cursor[i] = excl;
    }
}
__global__ void fill_csr(const int* __restrict__ src, const int* __restrict__ dst) {
    int e = blockIdx.x * blockDim.x + threadIdx.x;
    if (e < EE) {
        int p = atomicAdd(&g_cursor[dst[e]], 1);
        g_col[p] = src[e];
    }
}

// ---------------- mean aggregation: 2 nodes per warp, writes pre-split hi/lo ----
__device__ __forceinline__ void acc8(float* acc, uint4 v) {
    float2 t;
    t = __half22float2(*(__half2*)&v.x); acc[0] += t.x; acc[1] += t.y;
    t = __half22float2(*(__half2*)&v.y); acc[2] += t.x; acc[3] += t.y;
    t = __half22float2(*(__half2*)&v.z); acc[4] += t.x; acc[5] += t.y;
    t = __half22float2(*(__half2*)&v.w); acc[6] += t.x; acc[7] += t.y;
}
__global__ void __launch_bounds__(256) aggregate(int ibuf) {
    int gwarp = (blockIdx.x * 256 + threadIdx.x) >> 5;
    int lane = threadIdx.x & 31;
    int node = gwarp * 2 + (lane >> 4);
    int l16 = lane & 15;
    if (node >= NN) return;
    const __half* __restrict__ h = g_h[ibuf];
    int start = g_rowptr[node];
    int d = g_deg[node];
    float acc[8] = {0.f, 0.f, 0.f, 0.f, 0.f, 0.f, 0.f, 0.f};
    int j = 0;
    for (; j + 3 < d; j += 4) {
        int s0 = g_col[start + j];
        int s1 = g_col[start + j + 1];
        int s2 = g_col[start + j + 2];
        int s3 = g_col[start + j + 3];
        uint4 v0 = *(const uint4*)(h + s0 * HD + l16 * 8);
        uint4 v1 = *(const uint4*)(h + s1 * HD + l16 * 8);
        uint4 v2 = *(const uint4*)(h + s2 * HD + l16 * 8);
        uint4 v3 = *(const uint4*)(h + s3 * HD + l16 * 8);
        acc8(acc, v0); acc8(acc, v1); acc8(acc, v2); acc8(acc, v3);
    }
    for (; j < d; j++) {
        int s = g_col[start + j];
        uint4 v = *(const uint4*)(h + s * HD + l16 * 8);
        acc8(acc, v);
    }
    float inv = 1.f / (float)max(d, 1);
    uint2 whi, wlo;
    {
        float h0, l0, h1, l1, h2, l2, h3, l3;
        split2h(acc[0] * inv, h0, l0); split2h(acc[1] * inv, h1, l1);
        split2h(acc[2] * inv, h2, l2); split2h(acc[3] * inv, h3, l3);
        whi.x = pack2h(h0, h1); whi.y = pack2h(h2, h3);
        wlo.x = pack2h(l0, l1); wlo.y = pack2h(l2, l3);
    }
    *(uint2*)(g_aggh + node * HD + l16 * 8) = whi;
    *(uint2*)(g_aggl + node * HD + l16 * 8) = wlo;
    {
        float h0, l0, h1, l1, h2, l2, h3, l3;
        split2h(acc[4] * inv, h0, l0); split2h(acc[5] * inv, h1, l1);
        split2h(acc[6] * inv, h2, l2); split2h(acc[7] * inv, h3, l3);
        whi.x = pack2h(h0, h1); whi.y = pack2h(h2, h3);
        wlo.x = pack2h(l0, l1); wlo.y = pack2h(l2, l3);
    }
    *(uint2*)(g_aggh + node * HD + l16 * 8 + 4) = whi;
    *(uint2*)(g_aggl + node * HD + l16 * 8 + 4) = wlo;
}

// ---------------- fp16 split tensor-core GEMM + bias + LayerNorm + ReLU ----------------
// Block 128x128, 8 warps as 4x2 (warptile 32x64). K=256 logical:
//   kc 0..3: A = g_aggh/g_aggl (pre-split, 3 mma terms), B = Wl (pre-split)
//   kc 4..7: A = g_h (fp16 exact -> 2 terms),            B = Wr (pre-split)
// All staging is pure uint2 copies; no conversions in the mainloop.
#define KPW 20   // uint32 words per row per 32-k chunk (padded)

__global__ void __launch_bounds__(256) gemm_fused_f16(
    int ibuf, int layer,
    const float* __restrict__ bias, const float* __restrict__ gamma,
    const float* __restrict__ beta,
    int obuf, float* __restrict__ ext_out) {
    __shared__ uint32_t As_hi[128 * KPW], As_lo[128 * KPW];
    __shared__ uint32_t Bs_hi[128 * KPW], Bs_lo[128 * KPW];
    __shared__ float bias_s[128], gamma_s[128], beta_s[128];
    __shared__ float red[128 * 4];

    __half* __restrict__ out_h = g_h[obuf];
    const __half* __restrict__ Hp = g_h[ibuf];
    const __half* __restrict__ Bh = g_Whi[layer];
    const __half* __restrict__ Bl = g_Wlo[layer];

    int tid = threadIdx.x;
    int lane = tid & 31;
    int warp = tid >> 5;
    int g = lane >> 2;
    int t = lane & 3;
    int wrow = (warp >> 1) * 32;
    int wcol = (warp & 1) * 64;
    int brow = blockIdx.x * 128;

    if (tid < 128) {
        bias_s[tid] = bias[tid];
        gamma_s[tid] = gamma[tid];
        beta_s[tid] = beta[tid];
    }

    int arow = tid >> 3, akq = tid & 7;
    int agrow = brow + arow;

    float acc[2][8][4];
#pragma unroll
    for (int mi = 0; mi < 2; mi++)
#pragma unroll
        for (int ni = 0; ni < 8; ni++)
#pragma unroll
            for (int c = 0; c < 4; c++) acc[mi][ni][c] = 0.f;

    uint2 pa_hi[4], pa_lo[4], pb_hi[4], pb_lo[4];

    // ---- prefetch chunk 0 (agg + Wl) ----
#pragma unroll
    for (int it = 0; it < 4; it++) {
        int grow = agrow + it * 32;
        if (grow < NN) {
            pa_hi[it] = *(const uint2*)(g_aggh + grow * HD + akq * 4);
            pa_lo[it] = *(const uint2*)(g_aggl + grow * HD + akq * 4);
        } else {
            pa_hi[it] = make_uint2(0u, 0u);
            pa_lo[it] = make_uint2(0u, 0u);
        }
        pb_hi[it] = *(const uint2*)(Bh + (arow + it * 32) * HD + akq * 4);
        pb_lo[it] = *(const uint2*)(Bl + (arow + it * 32) * HD + akq * 4);
    }

    for (int kc = 0; kc < 8; kc++) {
        const bool isagg = (kc < 4);
        if (kc > 0) __syncthreads();
        // ---- store prefetched regs -> smem (pure copies) ----
#pragma unroll
        for (int it = 0; it < 4; it++) {
            int o = (arow + it * 32) * KPW + akq * 2;
            As_hi[o]     = pa_hi[it].x;
            As_hi[o + 1] = pa_hi[it].y;
            if (isagg) {
                As_lo[o]     = pa_lo[it].x;
                As_lo[o + 1] = pa_lo[it].y;
            }
            Bs_hi[o]     = pb_hi[it].x;
            Bs_hi[o + 1] = pb_hi[it].y;
            Bs_lo[o]     = pb_lo[it].x;
            Bs_lo[o + 1] = pb_lo[it].y;
        }
        __syncthreads();
        // ---- prefetch next chunk (LDGs overlap the mma below) ----
        if (kc < 7) {
            int kn = kc + 1;
            bool nagg = (kn < 4);
            int col0 = (kn * 32) & 127;
            if (nagg) {
#pragma unroll
                for (int it = 0; it < 4; it++) {
                    int grow = agrow + it * 32;
                    if (grow < NN) {
                        pa_hi[it] = *(const uint2*)(g_aggh + grow * HD + col0 + akq * 4);
                        pa_lo[it] = *(const uint2*)(g_aggl + grow * HD + col0 + akq * 4);
                    } else {
                        pa_hi[it] = make_uint2(0u, 0u);
                        pa_lo[it] = make_uint2(0u, 0u);
                    }
                }
            } else {
#pragma unroll
                for (int it = 0; it < 4; it++) {
                    int grow = agrow + it * 32;
                    pa_hi[it] = (grow < NN)
                                    ? *(const uint2*)(Hp + grow * HD + col0 + akq * 4)
                                    : make_uint2(0u, 0u);
                }
            }
            const __half* __restrict__ Bhp = Bh + (nagg ? 0 : HD * HD);
            const __half* __restrict__ Blp = Bl + (nagg ? 0 : HD * HD);
#pragma unroll
            for (int it = 0; it < 4; it++) {
                pb_hi[it] = *(const uint2*)(Bhp + (arow + it * 32) * HD + col0 + akq * 4);
                pb_lo[it] = *(const uint2*)(Blp + (arow + it * 32) * HD + col0 + akq * 4);
            }
        }
        // ---- mma on chunk kc ----
#pragma unroll
        for (int ks = 0; ks < 2; ks++) {
            int kw = ks * 8;
            uint32_t ah[2][4], al[2][4], bh[8][2], bl[8][2];
#pragma unroll
            for (int mi = 0; mi < 2; mi++) {
                int r0 = (wrow + mi * 16 + g) * KPW + kw;
                ah[mi][0] = As_hi[r0 + t];
                ah[mi][1] = As_hi[r0 + 8 * KPW + t];
                ah[mi][2] = As_hi[r0 + t + 4];
                ah[mi][3] = As_hi[r0 + 8 * KPW + t + 4];
                if (isagg) {
                    al[mi][0] = As_lo[r0 + t];
                    al[mi][1] = As_lo[r0 + 8 * KPW + t];
                    al[mi][2] = As_lo[r0 + t + 4];
                    al[mi][3] = As_lo[r0 + 8 * KPW + t + 4];
                }
            }
#pragma unroll
            for (int ni = 0; ni < 8; ni++) {
                int c0 = (wcol + ni * 8 + g) * KPW + kw;
                bh[ni][0] = Bs_hi[c0 + t];
                bh[ni][1] = Bs_hi[c0 + t + 4];
                bl[ni][0] = Bs_lo[c0 + t];
                bl[ni][1] = Bs_lo[c0 + t + 4];
            }
#pragma unroll
            for (int mi = 0; mi < 2; mi++)
#pragma unroll
                for (int ni = 0; ni < 8; ni++) {
                    mma_f16(acc[mi][ni], ah[mi][0], ah[mi][1], ah[mi][2], ah[mi][3],
                            bh[ni][0], bh[ni][1]);
                    if (isagg)
                        mma_f16(acc[mi][ni], al[mi][0], al[mi][1], al[mi][2], al[mi][3],
                                bh[ni][0], bh[ni][1]);
                    mma_f16(acc[mi][ni], ah[mi][0], ah[mi][1], ah[mi][2], ah[mi][3],
                            bl[ni][0], bl[ni][1]);
                }
        }
    }
    __syncthreads();

    // ---- epilogue: bias + LN(128 cols) + ReLU ----
    float ps[2][2], pq[2][2];
#pragma unroll
    for (int mi = 0; mi < 2; mi++)
#pragma unroll
        for (int h = 0; h < 2; h++) { ps[mi][h] = 0.f; pq[mi][h] = 0.f; }
#pragma unroll
    for (int mi = 0; mi < 2; mi++)
#pragma unroll
        for (int ni = 0; ni < 8; ni++) {
            int cbase = wcol + ni * 8 + 2 * t;
            float b0v = bias_s[cbase], b1v = bias_s[cbase + 1];
            float v;
            v = acc[mi][ni][0] + b0v; acc[mi][ni][0] = v; ps[mi][0] += v; pq[mi][0] += v * v;
            v = acc[mi][ni][1] + b1v; acc[mi][ni][1] = v; ps[mi][0] += v; pq[mi][0] += v * v;
            v = acc[mi][ni][2] + b0v; acc[mi][ni][2] = v; ps[mi][1] += v; pq[mi][1] += v * v;
            v = acc[mi][ni][3] + b1v; acc[mi][ni][3] = v; ps[mi][1] += v; pq[mi][1] += v * v;
        }
#pragma unroll
    for (int mi = 0; mi < 2; mi++)
#pragma unroll
        for (int h = 0; h < 2; h++) {
#pragma unroll
            for (int o = 1; o < 4; o <<= 1) {
                ps[mi][h] += __shfl_xor_sync(0xffffffffu, ps[mi][h], o);
                pq[mi][h] += __shfl_xor_sync(0xffffffffu, pq[mi][h], o);
            }
        }
    if (t == 0) {
#pragma unroll
        for (int mi = 0; mi < 2; mi++)
#pragma unroll
            for (int h = 0; h < 2; h++) {
                int rl = wrow + mi * 16 + h * 8 + g;
                red[rl * 4 + (warp & 1) * 2 + 0] = ps[mi][h];
                red[rl * 4 + (warp & 1) * 2 + 1] = pq[mi][h];
            }
    }
    __syncthreads();
#pragma unroll
    for (int mi = 0; mi < 2; mi++)
#pragma unroll
        for (int h = 0; h < 2; h++) {
            int rl = wrow + mi * 16 + h * 8 + g;
            float S = red[rl * 4 + 0] + red[rl * 4 + 2];
            float Q = red[rl * 4 + 1] + red[rl * 4 + 3];
            float mean = S * (1.f / HD);
            float var = Q * (1.f / HD) - mean * mean;
            float rstd = rsqrtf(var + EPS);
            int grow = brow + rl;
            if (grow < NN) {
#pragma unroll
                for (int ni = 0; ni < 8; ni++) {
                    int cbase = wcol + ni * 8 + 2 * t;
                    float v0 = acc[mi][ni][h * 2 + 0];
                    float v1 = acc[mi][ni][h * 2 + 1];
                    float o0 = fmaxf((v0 - mean) * rstd * gamma_s[cbase] + beta_s[cbase], 0.f);
                    float o1 = fmaxf((v1 - mean) * rstd * gamma_s[cbase + 1] + beta_s[cbase + 1], 0.f);
                    if (ext_out) {
                        *(float2*)(ext_out + grow * HD + cbase) = make_float2(o0, o1);
                    } else {
                        *(uint32_t*)(out_h + grow * HD + cbase) = pack2h(o0, o1);
                    }
                }
            }
        }
}

// ---------------- pooling ----------------
__global__ void pool_accum(const float* __restrict__ ne, const int* __restrict__ batch,
                           float* __restrict__ gout) {
    int tx = threadIdx.x;  // 128 = column
    int n0 = blockIdx.x * 128;
    int n1 = min(n0 + 128, NN);
    if (n0 >= NN) return;
    int cur = batch[n0];
    float sum = 0.f, mx = 0.f;
    for (int n = n0; n < n1; n++) {
        int b = batch[n];
        float v = ne[n * HD + tx];
        if (b != cur) {
            atomicAdd(&gout[cur * 256 + tx], sum);
            atomicMax((int*)&gout[cur * 256 + HD + tx], __float_as_int(mx));
            sum = 0.f; mx = 0.f; cur = b;
        }
        sum += v;
        mx = fmaxf(mx, v);
    }
    atomicAdd(&gout[cur * 256 + tx], sum);
    atomicMax((int*)&gout[cur * 256 + HD + tx], __float_as_int(mx));
}
__global__ void finalize_pool(float* __restrict__ gout) {
    int b = blockIdx.x;
    int tx = threadIdx.x;
    gout[b * 256 + tx] /= fmaxf(g_cnt[b], 1.f);
}

// ---------------- launch ----------------
extern "C" void kernel_launch(void* const* d_in, const int* in_sizes, int n_in,
                              void* d_out, int out_size) {
    const float* x   = (const float*)d_in[0];
    const int* ei    = (const int*)d_in[1];
    const int* batch = (const int*)d_in[2];
    const float* W0  = (const float*)d_in[3];
    const float* b0  = (const float*)d_in[4];
    const float* g0  = (const float*)d_in[5];
    const float* be0 = (const float*)d_in[6];
    const float* Wl1 = (const float*)d_in[7];
    const float* bl1 = (const float*)d_in[8];
    const float* Wr1 = (const float*)d_in[9];
    const float* g1  = (const float*)d_in[10];
    const float* be1 = (const float*)d_in[11];
    const float* Wl2 = (const float*)d_in[12];
    const float* bl2 = (const float*)d_in[13];
    const float* Wr2 = (const float*)d_in[14];
    const float* g2  = (const float*)d_in[15];
    const float* be2 = (const float*)d_in[16];
    const float* Wl3 = (const float*)d_in[17];
    const float* bl3 = (const float*)d_in[18];
    const float* Wr3 = (const float*)d_in[19];
    const float* g3  = (const float*)d_in[20];
    const float* be3 = (const float*)d_in[21];

    float* out = (float*)d_out;
    float* ne = out;                           // node_embed (N*H)
    float* gr = out + (size_t)NN * HD;         // graph_embed (B*2H)

    const int* src = ei;
    const int* dst = ei + EE;

    zero_misc<<<NB_SCAN, 256>>>(gr);
    split_w<<<(3 * 2 * HD * HD + 255) / 256, 256>>>(Wl1, Wr1, Wl2, Wr2, Wl3, Wr3);
    fat_start<<<EMB_BLOCKS + CD_BLOCKS + NB_SCAN, 256>>>(x, W0, b0, g0, be0, dst, batch);
    scan1<<<NB_SCAN, 256>>>();
    scan3<<<NB_SCAN, 256>>>();
    fill_csr<<<(EE + 255) / 256, 256>>>(src, dst);

    int gemm_blocks = (NN + 127) / 128;
    int agg_blocks = (NN / 2 * 32 + 255) / 256;

    // layer 1: h0 -> h1
    aggregate<<<agg_blocks, 256>>>(0);
    gemm_fused_f16<<<gemm_blocks, 256>>>(0, 0, bl1, g1, be1, 1, nullptr);
    // layer 2: h1 -> h0
    aggregate<<<agg_blocks, 256>>>(1);
    gemm_fused_f16<<<gemm_blocks, 256>>>(1, 1, bl2, g2, be2, 0, nullptr);
    // layer 3: h0 -> d_out node region (fp32)
    aggregate<<<agg_blocks, 256>>>(0);
    gemm_fused_f16<<<gemm_blocks, 256>>>(0, 2, bl3, g3, be3, 0, ne);

    pool_accum<<<(NN + 127) / 128, 128>>>(ne, batch, gr);
    finalize_pool<<<BG, 128>>>(gr);
}

// round 12
// speedup vs baseline: 1.3709x; 1.0562x over previous
#include <cuda_runtime.h>
#include <cuda_fp16.h>
#include <cstdint>

#define NN 100000
#define EE 1600000
#define BG 64
#define HD 128
#define DIN 9
#define EPS 1e-5f
#define NB_SCAN 391      // ceil(NN/256)
#define EMB_BLOCKS 3125  // 32 nodes per block
#define CD_BLOCKS 6250   // count_deg blocks
#define SW_BLOCKS 96     // split_w: 3*2*128*32 / 256

// ---------------- scratch (static __device__, no allocation) ----------------
__device__ __half g_h[2][NN * HD];        // ping-pong node features (fp16)
__device__ uint4  g_aggp[NN * 32];        // agg mean, packed {hi01,hi23,lo01,lo23} per 4k
__device__ uint4  g_Wsplit[3 * 2 * HD * 32]; // packed split weights [layer][part][c][kgroup]
__device__ int    g_deg[NN];
__device__ int    g_rowptr[NN];
__device__ int    g_cursor[NN];
__device__ int    g_col[EE];
__device__ int    g_bsum[512];
__device__ float  g_cnt[BG];

// ---------------- fp16 helpers ----------------
__device__ __forceinline__ uint32_t pack2h(float a, float b) {
    __half2 t = __floats2half2_rn(a, b);
    return *(uint32_t*)&t;
}
__device__ __forceinline__ void split2h(float x, float& hi, float& lo) {
    hi = __half2float(__float2half_rn(x));
    lo = x - hi;
}
__device__ __forceinline__ void mma_f16(float* c, uint32_t a0, uint32_t a1,
                                        uint32_t a2, uint32_t a3,
                                        uint32_t b0, uint32_t b1) {
    asm volatile(
        "mma.sync.aligned.m16n8k16.row.col.f32.f16.f16.f32 "
        "{%0,%1,%2,%3},{%4,%5,%6,%7},{%8,%9},{%0,%1,%2,%3};\n"
        : "+f"(c[0]), "+f"(c[1]), "+f"(c[2]), "+f"(c[3])
        : "r"(a0), "r"(a1), "r"(a2), "r"(a3), "r"(b0), "r"(b1));
}

// ---------------- prep: weight split-pack || zero (deg, cnt, pool out) ----------
__global__ void __launch_bounds__(256) prep(
    const float* __restrict__ Wl1, const float* __restrict__ Wr1,
    const float* __restrict__ Wl2, const float* __restrict__ Wr2,
    const float* __restrict__ Wl3, const float* __restrict__ Wr3,
    float* __restrict__ gr) {
    int bid = blockIdx.x;
    if (bid < SW_BLOCKS) {
        int idx = bid * 256 + threadIdx.x;     // group index, 0 .. 24575
        int l = idx / 8192;                    // 2*128*32 = 8192 groups per layer
        int rem = idx - l * 8192;
        int part = rem >> 12;                  // 128*32 = 4096
        int cg = rem & 4095;                   // c*32 + g
        const float* W;
        if (l == 0) W = part ? Wr1 : Wl1;
        else if (l == 1) W = part ? Wr2 : Wl2;
        else W = part ? Wr3 : Wl3;
        float4 v = *(const float4*)(W + cg * 4);
        float h0, l0, h1, l1, h2, l2, h3, l3;
        split2h(v.x, h0, l0); split2h(v.y, h1, l1);
        split2h(v.z, h2, l2); split2h(v.w, h3, l3);
        uint4 w;
        w.x = pack2h(h0, h1); w.y = pack2h(h2, h3);
        w.z = pack2h(l0, l1); w.w = pack2h(l2, l3);
        g_Wsplit[idx] = w;
    } else {
        int i = (bid - SW_BLOCKS) * 256 + threadIdx.x;
        if (i < NN) g_deg[i] = 0;
        if (i < BG * 2 * HD) gr[i] = 0.f;
        if (i < BG) g_cnt[i] = 0.f;
    }
}

// ---------------- fat start: embed || count_deg || count_batch ----------------
__global__ void __launch_bounds__(256) fat_start(
    const float* __restrict__ x, const float* __restrict__ W0,
    const float* __restrict__ b0, const float* __restrict__ g0,
    const float* __restrict__ be0,
    const int* __restrict__ dst, const int* __restrict__ batch) {
    int bid = blockIdx.x;
    int tid = threadIdx.x;
    if (bid < EMB_BLOCKS) {
        __shared__ float Ws[HD * DIN];
        __shared__ float bs[HD], gs[HD], es[HD];
        for (int i = tid; i < HD * DIN; i += 256) Ws[i] = W0[i];
        if (tid < HD) { bs[tid] = b0[tid]; gs[tid] = g0[tid]; es[tid] = be0[tid]; }
        __syncthreads();
        int warp = tid >> 5;
        int lane = tid & 31;
        __half* hout = g_h[0];
#pragma unroll
        for (int it = 0; it < 4; it++) {
            int n = bid * 32 + it * 8 + warp;   // always < NN (3125*32 == NN)
            float xv = (lane < DIN) ? x[n * DIN + lane] : 0.f;
            float xj[DIN];
#pragma unroll
            for (int j = 0; j < DIN; j++) xj[j] = __shfl_sync(0xffffffffu, xv, j);
            float val[4];
#pragma unroll
            for (int q = 0; q < 4; q++) {
                int f = lane * 4 + q;
                float v = bs[f];
#pragma unroll
                for (int j = 0; j < DIN; j++) v += xj[j] * Ws[f * DIN + j];
                val[q] = v;
            }
            float s = val[0] + val[1] + val[2] + val[3];
            float s2 = val[0]*val[0] + val[1]*val[1] + val[2]*val[2] + val[3]*val[3];
#pragma unroll
            for (int o = 16; o; o >>= 1) {
                s += __shfl_xor_sync(0xffffffffu, s, o);
                s2 += __shfl_xor_sync(0xffffffffu, s2, o);
            }
            float mean = s * (1.f / HD);
            float var = s2 * (1.f / HD) - mean * mean;
            float rstd = rsqrtf(var + EPS);
            uint2 w;
            {
                int f = lane * 4;
                float o0 = fmaxf((val[0] - mean) * rstd * gs[f] + es[f], 0.f);
                float o1 = fmaxf((val[1] - mean) * rstd * gs[f+1] + es[f+1], 0.f);
                float o2 = fmaxf((val[2] - mean) * rstd * gs[f+2] + es[f+2], 0.f);
                float o3 = fmaxf((val[3] - mean) * rstd * gs[f+3] + es[f+3], 0.f);
                w.x = pack2h(o0, o1);
                w.y = pack2h(o2, o3);
            }
            *(uint2*)(hout + n * HD + lane * 4) = w;
        }
    } else if (bid < EMB_BLOCKS + CD_BLOCKS) {
        int e = (bid - EMB_BLOCKS) * 256 + tid;
        if (e < EE) atomicAdd(&g_deg[dst[e]], 1);
    } else {
        int i = (bid - EMB_BLOCKS - CD_BLOCKS) * 256 + tid;
        if (i < NN) atomicAdd(&g_cnt[batch[i]], 1.f);
    }
}

// ---------------- CSR scans + fill ----------------
__global__ void scan1() {
    __shared__ int sm[256];
    int t = threadIdx.x;
    int i = blockIdx.x * 256 + t;
    sm[t] = (i < NN) ? g_deg[i] : 0;
    __syncthreads();
#pragma unroll
    for (int o = 128; o; o >>= 1) {
        if (t < o) sm[t] += sm[t + o];
        __syncthreads();
    }
    if (t == 0) g_bsum[blockIdx.x] = sm[0];
}
// scan3 computes its own block offset by reducing g_bsum[0..bid-1]
__global__ void scan3() {
    __shared__ int sm[256];
    __shared__ int offsh;
    int t = threadIdx.x;
    int partial = 0;
    for (int i = t; i < blockIdx.x; i += 256) partial += g_bsum[i];
#pragma unroll
    for (int o = 16; o; o >>= 1) partial += __shfl_xor_sync(0xffffffffu, partial, o);
    if ((t & 31) == 0) sm[t >> 5] = partial;
    __syncthreads();
    if (t == 0) {
        int s = 0;
#pragma unroll
        for (int w = 0; w < 8; w++) s += sm[w];
        offsh = s;
    }
    __syncthreads();
    int boff = offsh;
    __syncthreads();
    int i = blockIdx.x * 256 + t;
    int v = (i < NN) ? g_deg[i] : 0;
    sm[t] = v;
    __syncthreads();
    for (int o = 1; o < 256; o <<= 1) {
        int add = (t >= o) ? sm[t - o] : 0;
        __syncthreads();
        sm[t] += add;
        __syncthreads();
    }
    if (i < NN) {
        int excl = sm[t] - v + boff;
        g_rowptr[i] = excl;
        g_cursor[i] = excl;
    }
}
__global__ void fill_csr(const int* __restrict__ src, const int* __restrict__ dst) {
    int e = blockIdx.x * blockDim.x + threadIdx.x;
    if (e < EE) {
        int p = atomicAdd(&g_cursor[dst[e]], 1);
        g_col[p] = src[e];
    }
}

// ---------------- mean aggregation: 2 nodes/warp, packed hi/lo output ----------
__device__ __forceinline__ void acc8(float* acc, uint4 v) {
    float2 t;
    t = __half22float2(*(__half2*)&v.x); acc[0] += t.x; acc[1] += t.y;
    t = __half22float2(*(__half2*)&v.y); acc[2] += t.x; acc[3] += t.y;
    t = __half22float2(*(__half2*)&v.z); acc[4] += t.x; acc[5] += t.y;
    t = __half22float2(*(__half2*)&v.w); acc[6] += t.x; acc[7] += t.y;
}
__global__ void __launch_bounds__(256) aggregate(int ibuf) {
    int gwarp = (blockIdx.x * 256 + threadIdx.x) >> 5;
    int lane = threadIdx.x & 31;
    int node = gwarp * 2 + (lane >> 4);
    int l16 = lane & 15;
    if (node >= NN) return;
    const __half* __restrict__ h = g_h[ibuf];
    int start = g_rowptr[node];
    int d = g_deg[node];
    float acc[8] = {0.f, 0.f, 0.f, 0.f, 0.f, 0.f, 0.f, 0.f};
    int j = 0;
    for (; j + 3 < d; j += 4) {
        int s0 = g_col[start + j];
        int s1 = g_col[start + j + 1];
        int s2 = g_col[start + j + 2];
        int s3 = g_col[start + j + 3];
        uint4 v0 = *(const uint4*)(h + s0 * HD + l16 * 8);
        uint4 v1 = *(const uint4*)(h + s1 * HD + l16 * 8);
        uint4 v2 = *(const uint4*)(h + s2 * HD + l16 * 8);
        uint4 v3 = *(const uint4*)(h + s3 * HD + l16 * 8);
        acc8(acc, v0); acc8(acc, v1); acc8(acc, v2); acc8(acc, v3);
    }
    for (; j < d; j++) {
        int s = g_col[start + j];
        uint4 v = *(const uint4*)(h + s * HD + l16 * 8);
        acc8(acc, v);
    }
    float inv = 1.f / (float)max(d, 1);
    uint4 w;
    {
        float h0, l0, h1, l1, h2, l2, h3, l3;
        split2h(acc[0] * inv, h0, l0); split2h(acc[1] * inv, h1, l1);
        split2h(acc[2] * inv, h2, l2); split2h(acc[3] * inv, h3, l3);
        w.x = pack2h(h0, h1); w.y = pack2h(h2, h3);
        w.z = pack2h(l0, l1); w.w = pack2h(l2, l3);
    }
    g_aggp[node * 32 + l16 * 2] = w;
    {
        float h0, l0, h1, l1, h2, l2, h3, l3;
        split2h(acc[4] * inv, h0, l0); split2h(acc[5] * inv, h1, l1);
        split2h(acc[6] * inv, h2, l2); split2h(acc[7] * inv, h3, l3);
        w.x = pack2h(h0, h1); w.y = pack2h(h2, h3);
        w.z = pack2h(l0, l1); w.w = pack2h(l2, l3);
    }
    g_aggp[node * 32 + l16 * 2 + 1] = w;
}

// ---------------- fp16 split tensor-core GEMM + bias + LayerNorm + ReLU ----------------
// Block 128x128, 8 warps as 4x2 (warptile 32x64). K=256 logical:
//   kc 0..3: A = g_aggp (packed hi/lo, 3 mma terms), B = Wl (packed)
//   kc 4..7: A = g_h (fp16 exact -> 2 terms),        B = Wr (packed)
// Every global op is 16B (A-h half: 8B); staging is pure register moves.
#define KPW 20   // uint32 words per row per 32-k chunk (padded)

__global__ void __launch_bounds__(256) gemm_fused_f16(
    int ibuf, int layer,
    const float* __restrict__ bias, const float* __restrict__ gamma,
    const float* __restrict__ beta,
    int obuf, float* __restrict__ ext_out) {
    __shared__ uint32_t As_hi[128 * KPW], As_lo[128 * KPW];
    __shared__ uint32_t Bs_hi[128 * KPW], Bs_lo[128 * KPW];
    __shared__ float bias_s[128], gamma_s[128], beta_s[128];
    __shared__ float red[128 * 4];

    __half* __restrict__ out_h = g_h[obuf];
    const __half* __restrict__ Hp = g_h[ibuf];
    const uint4* __restrict__ Wsp = g_Wsplit + layer * 2 * HD * 32;

    int tid = threadIdx.x;
    int lane = tid & 31;
    int warp = tid >> 5;
    int g = lane >> 2;
    int t = lane & 3;
    int wrow = (warp >> 1) * 32;
    int wcol = (warp & 1) * 64;
    int brow = blockIdx.x * 128;

    if (tid < 128) {
        bias_s[tid] = bias[tid];
        gamma_s[tid] = gamma[tid];
        beta_s[tid] = beta[tid];
    }

    int arow = tid >> 3, akq = tid & 7;
    int agrow = brow + arow;

    float acc[2][8][4];
#pragma unroll
    for (int mi = 0; mi < 2; mi++)
#pragma unroll
        for (int ni = 0; ni < 8; ni++)
#pragma unroll
            for (int c = 0; c < 4; c++) acc[mi][ni][c] = 0.f;

    uint4 pa[4];    // packed agg hi/lo (agg half)
    uint2 pah[4];   // fp16 h (root half)
    uint4 pbw[4];   // packed weights hi/lo

    // ---- prefetch chunk 0 (agg + Wl) ----
#pragma unroll
    for (int it = 0; it < 4; it++) {
        int grow = agrow + it * 32;
        pa[it] = (grow < NN) ? g_aggp[grow * 32 + akq]
                             : make_uint4(0u, 0u, 0u, 0u);
        pbw[it] = Wsp[(arow + it * 32) * 32 + akq];
    }

    for (int kc = 0; kc < 8; kc++) {
        const bool isagg = (kc < 4);
        if (kc > 0) __syncthreads();
        // ---- store prefetched regs -> smem (pure moves) ----
#pragma unroll
        for (int it = 0; it < 4; it++) {
            int o = (arow + it * 32) * KPW + akq * 2;
            if (isagg) {
                As_hi[o]     = pa[it].x;
                As_hi[o + 1] = pa[it].y;
                As_lo[o]     = pa[it].z;
                As_lo[o + 1] = pa[it].w;
            } else {
                As_hi[o]     = pah[it].x;
                As_hi[o + 1] = pah[it].y;
            }
            Bs_hi[o]     = pbw[it].x;
            Bs_hi[o + 1] = pbw[it].y;
            Bs_lo[o]     = pbw[it].z;
            Bs_lo[o + 1] = pbw[it].w;
        }
        __syncthreads();
        // ---- prefetch next chunk (LDGs overlap the mma below) ----
        if (kc < 7) {
            int kn = kc + 1;
            bool nagg = (kn < 4);
            int gq = (kn & 3) * 8 + akq;       // k-group within 128
            if (nagg) {
#pragma unroll
                for (int it = 0; it < 4; it++) {
                    int grow = agrow + it * 32;
                    pa[it] = (grow < NN) ? g_aggp[grow * 32 + gq]
                                         : make_uint4(0u, 0u, 0u, 0u);
                }
            } else {
                int col0 = (kn & 3) * 32;
#pragma unroll
                for (int it = 0; it < 4; it++) {
                    int grow = agrow + it * 32;
                    pah[it] = (grow < NN)
                                  ? *(const uint2*)(Hp + grow * HD + col0 + akq * 4)
                                  : make_uint2(0u, 0u);
                }
            }
            const uint4* __restrict__ Wp = Wsp + (nagg ? 0 : HD * 32);
#pragma unroll
            for (int it = 0; it < 4; it++)
                pbw[it] = Wp[(arow + it * 32) * 32 + gq];
        }
        // ---- mma on chunk kc ----
#pragma unroll
        for (int ks = 0; ks < 2; ks++) {
            int kw = ks * 8;
            uint32_t ah[2][4], al[2][4], bh[8][2], bl[8][2];
#pragma unroll
            for (int mi = 0; mi < 2; mi++) {
                int r0 = (wrow + mi * 16 + g) * KPW + kw;
                ah[mi][0] = As_hi[r0 + t];
                ah[mi][1] = As_hi[r0 + 8 * KPW + t];
                ah[mi][2] = As_hi[r0 + t + 4];
                ah[mi][3] = As_hi[r0 + 8 * KPW + t + 4];
                if (isagg) {
                    al[mi][0] = As_lo[r0 + t];
                    al[mi][1] = As_lo[r0 + 8 * KPW + t];
                    al[mi][2] = As_lo[r0 + t + 4];
                    al[mi][3] = As_lo[r0 + 8 * KPW + t + 4];
                }
            }
#pragma unroll
            for (int ni = 0; ni < 8; ni++) {
                int c0 = (wcol + ni * 8 + g) * KPW + kw;
                bh[ni][0] = Bs_hi[c0 + t];
                bh[ni][1] = Bs_hi[c0 + t + 4];
                bl[ni][0] = Bs_lo[c0 + t];
                bl[ni][1] = Bs_lo[c0 + t + 4];
            }
#pragma unroll
            for (int mi = 0; mi < 2; mi++)
#pragma unroll
                for (int ni = 0; ni < 8; ni++) {
                    mma_f16(acc[mi][ni], ah[mi][0], ah[mi][1], ah[mi][2], ah[mi][3],
                            bh[ni][0], bh[ni][1]);
                    if (isagg)
                        mma_f16(acc[mi][ni], al[mi][0], al[mi][1], al[mi][2], al[mi][3],
                                bh[ni][0], bh[ni][1]);
                    mma_f16(acc[mi][ni], ah[mi][0], ah[mi][1], ah[mi][2], ah[mi][3],
                            bl[ni][0], bl[ni][1]);
                }
        }
    }
    __syncthreads();

    // ---- epilogue: bias + LN(128 cols) + ReLU ----
    float ps[2][2], pq[2][2];
#pragma unroll
    for (int mi = 0; mi < 2; mi++)
#pragma unroll
        for (int h = 0; h < 2; h++) { ps[mi][h] = 0.f; pq[mi][h] = 0.f; }
#pragma unroll
    for (int mi = 0; mi < 2; mi++)
#pragma unroll
        for (int ni = 0; ni < 8; ni++) {
            int cbase = wcol + ni * 8 + 2 * t;
            float b0v = bias_s[cbase], b1v = bias_s[cbase + 1];
            float v;
            v = acc[mi][ni][0] + b0v; acc[mi][ni][0] = v; ps[mi][0] += v; pq[mi][0] += v * v;
            v = acc[mi][ni][1] + b1v; acc[mi][ni][1] = v; ps[mi][0] += v; pq[mi][0] += v * v;
            v = acc[mi][ni][2] + b0v; acc[mi][ni][2] = v; ps[mi][1] += v; pq[mi][1] += v * v;
            v = acc[mi][ni][3] + b1v; acc[mi][ni][3] = v; ps[mi][1] += v; pq[mi][1] += v * v;
        }
#pragma unroll
    for (int mi = 0; mi < 2; mi++)
#pragma unroll
        for (int h = 0; h < 2; h++) {
#pragma unroll
            for (int o = 1; o < 4; o <<= 1) {
                ps[mi][h] += __shfl_xor_sync(0xffffffffu, ps[mi][h], o);
                pq[mi][h] += __shfl_xor_sync(0xffffffffu, pq[mi][h], o);
            }
        }
    if (t == 0) {
#pragma unroll
        for (int mi = 0; mi < 2; mi++)
#pragma unroll
            for (int h = 0; h < 2; h++) {
                int rl = wrow + mi * 16 + h * 8 + g;
                red[rl * 4 + (warp & 1) * 2 + 0] = ps[mi][h];
                red[rl * 4 + (warp & 1) * 2 + 1] = pq[mi][h];
            }
    }
    __syncthreads();
#pragma unroll
    for (int mi = 0; mi < 2; mi++)
#pragma unroll
        for (int h = 0; h < 2; h++) {
            int rl = wrow + mi * 16 + h * 8 + g;
            float S = red[rl * 4 + 0] + red[rl * 4 + 2];
            float Q = red[rl * 4 + 1] + red[rl * 4 + 3];
            float mean = S * (1.f / HD);
            float var = Q * (1.f / HD) - mean * mean;
            float rstd = rsqrtf(var + EPS);
            int grow = brow + rl;
            if (grow < NN) {
#pragma unroll
                for (int ni = 0; ni < 8; ni++) {
                    int cbase = wcol + ni * 8 + 2 * t;
                    float v0 = acc[mi][ni][h * 2 + 0];
                    float v1 = acc[mi][ni][h * 2 + 1];
                    float o0 = fmaxf((v0 - mean) * rstd * gamma_s[cbase] + beta_s[cbase], 0.f);
                    float o1 = fmaxf((v1 - mean) * rstd * gamma_s[cbase + 1] + beta_s[cbase + 1], 0.f);
                    if (ext_out) {
                        *(float2*)(ext_out + grow * HD + cbase) = make_float2(o0, o1);
                    } else {
                        *(uint32_t*)(out_h + grow * HD + cbase) = pack2h(o0, o1);
                    }
                }
            }
        }
}

// ---------------- pooling ----------------
__global__ void pool_accum(const float* __restrict__ ne, const int* __restrict__ batch,
                           float* __restrict__ gout) {
    int tx = threadIdx.x;  // 128 = column
    int n0 = blockIdx.x * 128;
    int n1 = min(n0 + 128, NN);
    if (n0 >= NN) return;
    int cur = batch[n0];
    float sum = 0.f, mx = 0.f;
    for (int n = n0; n < n1; n++) {
        int b = batch[n];
        float v = ne[n * HD + tx];
        if (b != cur) {
            atomicAdd(&gout[cur * 256 + tx], sum);
            atomicMax((int*)&gout[cur * 256 + HD + tx], __float_as_int(mx));
            sum = 0.f; mx = 0.f; cur = b;
        }
        sum += v;
        mx = fmaxf(mx, v);
    }
    atomicAdd(&gout[cur * 256 + tx], sum);
    atomicMax((int*)&gout[cur * 256 + HD + tx], __float_as_int(mx));
}
__global__ void finalize_pool(float* __restrict__ gout) {
    int b = blockIdx.x;
    int tx = threadIdx.x;
    gout[b * 256 + tx] /= fmaxf(g_cnt[b], 1.f);
}

// ---------------- launch ----------------
extern "C" void kernel_launch(void* const* d_in, const int* in_sizes, int n_in,
                              void* d_out, int out_size) {
    const float* x   = (const float*)d_in[0];
    const int* ei    = (const int*)d_in[1];
    const int* batch = (const int*)d_in[2];
    const float* W0  = (const float*)d_in[3];
    const float* b0  = (const float*)d_in[4];
    const float* g0  = (const float*)d_in[5];
    const float* be0 = (const float*)d_in[6];
    const float* Wl1 = (const float*)d_in[7];
    const float* bl1 = (const float*)d_in[8];
    const float* Wr1 = (const float*)d_in[9];
    const float* g1  = (const float*)d_in[10];
    const float* be1 = (const float*)d_in[11];
    const float* Wl2 = (const float*)d_in[12];
    const float* bl2 = (const float*)d_in[13];
    const float* Wr2 = (const float*)d_in[14];
    const float* g2  = (const float*)d_in[15];
    const float* be2 = (const float*)d_in[16];
    const float* Wl3 = (const float*)d_in[17];
    const float* bl3 = (const float*)d_in[18];
    const float* Wr3 = (const float*)d_in[19];
    const float* g3  = (const float*)d_in[20];
    const float* be3 = (const float*)d_in[21];

    float* out = (float*)d_out;
    float* ne = out;                           // node_embed (N*H)
    float* gr = out + (size_t)NN * HD;         // graph_embed (B*2H)

    const int* src = ei;
    const int* dst = ei + EE;

    prep<<<SW_BLOCKS + NB_SCAN, 256>>>(Wl1, Wr1, Wl2, Wr2, Wl3, Wr3, gr);
    fat_start<<<EMB_BLOCKS + CD_BLOCKS + NB_SCAN, 256>>>(x, W0, b0, g0, be0, dst, batch);
    scan1<<<NB_SCAN, 256>>>();
    scan3<<<NB_SCAN, 256>>>();
    fill_csr<<<(EE + 255) / 256, 256>>>(src, dst);

    int gemm_blocks = (NN + 127) / 128;
    int agg_blocks = (NN / 2 * 32 + 255) / 256;

    // layer 1: h0 -> h1
    aggregate<<<agg_blocks, 256>>>(0);
    gemm_fused_f16<<<gemm_blocks, 256>>>(0, 0, bl1, g1, be1, 1, nullptr);
    // layer 2: h1 -> h0
    aggregate<<<agg_blocks, 256>>>(1);
    gemm_fused_f16<<<gemm_blocks, 256>>>(1, 1, bl2, g2, be2, 0, nullptr);
    // layer 3: h0 -> d_out node region (fp32)
    aggregate<<<agg_blocks, 256>>>(0);
    gemm_fused_f16<<<gemm_blocks, 256>>>(0, 2, bl3, g3, be3, 0, ne);

    pool_accum<<<(NN + 127) / 128, 128>>>(ne, batch, gr);
    finalize_pool<<<BG, 128>>>(gr);
}

// round 13
// speedup vs baseline: 1.4163x; 1.0331x over previous
#include <cuda_runtime.h>
#include <cuda_fp16.h>
#include <cstdint>

#define NN 100000
#define EE 1600000
#define BG 64
#define HD 128
#define DIN 9
#define EPS 1e-5f
#define NB_SCAN 391      // ceil(NN/256)
#define EMB_BLOCKS 3125  // 32 nodes per block
#define CD_BLOCKS 6250   // count_deg blocks
#define SW_BLOCKS 96     // split_w: 3*2*128*32 / 256

// ---------------- scratch (static __device__, no allocation) ----------------
__device__ __half g_h[2][NN * HD];        // ping-pong node features (fp16)
__device__ uint4  g_agg4[NN * 16];        // agg mean fp16 (hi only), uint4 per 8 k
__device__ uint4  g_Wsplit[3 * 2 * HD * 32]; // packed split weights {hi01,hi23,lo01,lo23}/4k
__device__ int    g_deg[NN];
__device__ int    g_rowptr[NN];
__device__ int    g_cursor[NN];
__device__ int    g_col[EE];
__device__ int    g_bsum[512];
__device__ float  g_cnt[BG];

// ---------------- fp16 helpers ----------------
__device__ __forceinline__ uint32_t pack2h(float a, float b) {
    __half2 t = __floats2half2_rn(a, b);
    return *(uint32_t*)&t;
}
__device__ __forceinline__ void split2h(float x, float& hi, float& lo) {
    hi = __half2float(__float2half_rn(x));
    lo = x - hi;
}
__device__ __forceinline__ void mma_f16(float* c, uint32_t a0, uint32_t a1,
                                        uint32_t a2, uint32_t a3,
                                        uint32_t b0, uint32_t b1) {
    asm volatile(
        "mma.sync.aligned.m16n8k16.row.col.f32.f16.f16.f32 "
        "{%0,%1,%2,%3},{%4,%5,%6,%7},{%8,%9},{%0,%1,%2,%3};\n"
        : "+f"(c[0]), "+f"(c[1]), "+f"(c[2]), "+f"(c[3])
        : "r"(a0), "r"(a1), "r"(a2), "r"(a3), "r"(b0), "r"(b1));
}

// ---------------- prep: weight split-pack || zero (deg, cnt, pool out) ----------
__global__ void __launch_bounds__(256) prep(
    const float* __restrict__ Wl1, const float* __restrict__ Wr1,
    const float* __restrict__ Wl2, const float* __restrict__ Wr2,
    const float* __restrict__ Wl3, const float* __restrict__ Wr3,
    float* __restrict__ gr) {
    int bid = blockIdx.x;
    if (bid < SW_BLOCKS) {
        int idx = bid * 256 + threadIdx.x;     // group index, 0 .. 24575
        int l = idx / 8192;                    // 2*128*32 = 8192 groups per layer
        int rem = idx - l * 8192;
        int part = rem >> 12;                  // 128*32 = 4096
        int cg = rem & 4095;                   // c*32 + g
        const float* W;
        if (l == 0) W = part ? Wr1 : Wl1;
        else if (l == 1) W = part ? Wr2 : Wl2;
        else W = part ? Wr3 : Wl3;
        float4 v = *(const float4*)(W + cg * 4);
        float h0, l0, h1, l1, h2, l2, h3, l3;
        split2h(v.x, h0, l0); split2h(v.y, h1, l1);
        split2h(v.z, h2, l2); split2h(v.w, h3, l3);
        uint4 w;
        w.x = pack2h(h0, h1); w.y = pack2h(h2, h3);
        w.z = pack2h(l0, l1); w.w = pack2h(l2, l3);
        g_Wsplit[idx] = w;
    } else {
        int i = (bid - SW_BLOCKS) * 256 + threadIdx.x;
        if (i < NN) g_deg[i] = 0;
        if (i < BG * 2 * HD) gr[i] = 0.f;
        if (i < BG) g_cnt[i] = 0.f;
    }
}

// ---------------- fat start: embed || count_deg || count_batch ----------------
__global__ void __launch_bounds__(256) fat_start(
    const float* __restrict__ x, const float* __restrict__ W0,
    const float* __restrict__ b0, const float* __restrict__ g0,
    const float* __restrict__ be0,
    const int* __restrict__ dst, const int* __restrict__ batch) {
    int bid = blockIdx.x;
    int tid = threadIdx.x;
    if (bid < EMB_BLOCKS) {
        __shared__ float Ws[HD * DIN];
        __shared__ float bs[HD], gs[HD], es[HD];
        for (int i = tid; i < HD * DIN; i += 256) Ws[i] = W0[i];
        if (tid < HD) { bs[tid] = b0[tid]; gs[tid] = g0[tid]; es[tid] = be0[tid]; }
        __syncthreads();
        int warp = tid >> 5;
        int lane = tid & 31;
        __half* hout = g_h[0];
#pragma unroll
        for (int it = 0; it < 4; it++) {
            int n = bid * 32 + it * 8 + warp;   // always < NN (3125*32 == NN)
            float xv = (lane < DIN) ? x[n * DIN + lane] : 0.f;
            float xj[DIN];
#pragma unroll
            for (int j = 0; j < DIN; j++) xj[j] = __shfl_sync(0xffffffffu, xv, j);
            float val[4];
#pragma unroll
            for (int q = 0; q < 4; q++) {
                int f = lane * 4 + q;
                float v = bs[f];
#pragma unroll
                for (int j = 0; j < DIN; j++) v += xj[j] * Ws[f * DIN + j];
                val[q] = v;
            }
            float s = val[0] + val[1] + val[2] + val[3];
            float s2 = val[0]*val[0] + val[1]*val[1] + val[2]*val[2] + val[3]*val[3];
#pragma unroll
            for (int o = 16; o; o >>= 1) {
                s += __shfl_xor_sync(0xffffffffu, s, o);
                s2 += __shfl_xor_sync(0xffffffffu, s2, o);
            }
            float mean = s * (1.f / HD);
            float var = s2 * (1.f / HD) - mean * mean;
            float rstd = rsqrtf(var + EPS);
            uint2 w;
            {
                int f = lane * 4;
                float o0 = fmaxf((val[0] - mean) * rstd * gs[f] + es[f], 0.f);
                float o1 = fmaxf((val[1] - mean) * rstd * gs[f+1] + es[f+1], 0.f);
                float o2 = fmaxf((val[2] - mean) * rstd * gs[f+2] + es[f+2], 0.f);
                float o3 = fmaxf((val[3] - mean) * rstd * gs[f+3] + es[f+3], 0.f);
                w.x = pack2h(o0, o1);
                w.y = pack2h(o2, o3);
            }
            *(uint2*)(hout + n * HD + lane * 4) = w;
        }
    } else if (bid < EMB_BLOCKS + CD_BLOCKS) {
        int e = (bid - EMB_BLOCKS) * 256 + tid;
        if (e < EE) atomicAdd(&g_deg[dst[e]], 1);
    } else {
        int i = (bid - EMB_BLOCKS - CD_BLOCKS) * 256 + tid;
        if (i < NN) atomicAdd(&g_cnt[batch[i]], 1.f);
    }
}

// ---------------- CSR scans + fill ----------------
__global__ void scan1() {
    __shared__ int sm[256];
    int t = threadIdx.x;
    int i = blockIdx.x * 256 + t;
    sm[t] = (i < NN) ? g_deg[i] : 0;
    __syncthreads();
#pragma unroll
    for (int o = 128; o; o >>= 1) {
        if (t < o) sm[t] += sm[t + o];
        __syncthreads();
    }
    if (t == 0) g_bsum[blockIdx.x] = sm[0];
}
// scan3 computes its own block offset by reducing g_bsum[0..bid-1]
__global__ void scan3() {
    __shared__ int sm[256];
    __shared__ int offsh;
    int t = threadIdx.x;
    int partial = 0;
    for (int i = t; i < blockIdx.x; i += 256) partial += g_bsum[i];
#pragma unroll
    for (int o = 16; o; o >>= 1) partial += __shfl_xor_sync(0xffffffffu, partial, o);
    if ((t & 31) == 0) sm[t >> 5] = partial;
    __syncthreads();
    if (t == 0) {
        int s = 0;
#pragma unroll
        for (int w = 0; w < 8; w++) s += sm[w];
        offsh = s;
    }
    __syncthreads();
    int boff = offsh;
    __syncthreads();
    int i = blockIdx.x * 256 + t;
    int v = (i < NN) ? g_deg[i] : 0;
    sm[t] = v;
    __syncthreads();
    for (int o = 1; o < 256; o <<= 1) {
        int add = (t >= o) ? sm[t - o] : 0;
        __syncthreads();
        sm[t] += add;
        __syncthreads();
    }
    if (i < NN) {
        int excl = sm[t] - v + boff;
        g_rowptr[i] = excl;
        g_cursor[i] = excl;
    }
}
__global__ void fill_csr(const int* __restrict__ src, const int* __restrict__ dst) {
    int e = blockIdx.x * blockDim.x + threadIdx.x;
    if (e < EE) {
        int p = atomicAdd(&g_cursor[dst[e]], 1);
        g_col[p] = src[e];
    }
}

// ---------------- mean aggregation: 2 nodes/warp, fp16 hi output (one uint4/lane) --
__device__ __forceinline__ void acc8(float* acc, uint4 v) {
    float2 t;
    t = __half22float2(*(__half2*)&v.x); acc[0] += t.x; acc[1] += t.y;
    t = __half22float2(*(__half2*)&v.y); acc[2] += t.x; acc[3] += t.y;
    t = __half22float2(*(__half2*)&v.z); acc[4] += t.x; acc[5] += t.y;
    t = __half22float2(*(__half2*)&v.w); acc[6] += t.x; acc[7] += t.y;
}
__global__ void __launch_bounds__(256) aggregate(int ibuf) {
    int gwarp = (blockIdx.x * 256 + threadIdx.x) >> 5;
    int lane = threadIdx.x & 31;
    int node = gwarp * 2 + (lane >> 4);
    int l16 = lane & 15;
    if (node >= NN) return;
    const __half* __restrict__ h = g_h[ibuf];
    int start = g_rowptr[node];
    int d = g_deg[node];
    float acc[8] = {0.f, 0.f, 0.f, 0.f, 0.f, 0.f, 0.f, 0.f};
    int j = 0;
    for (; j + 3 < d; j += 4) {
        int s0 = g_col[start + j];
        int s1 = g_col[start + j + 1];
        int s2 = g_col[start + j + 2];
        int s3 = g_col[start + j + 3];
        uint4 v0 = *(const uint4*)(h + s0 * HD + l16 * 8);
        uint4 v1 = *(const uint4*)(h + s1 * HD + l16 * 8);
        uint4 v2 = *(const uint4*)(h + s2 * HD + l16 * 8);
        uint4 v3 = *(const uint4*)(h + s3 * HD + l16 * 8);
        acc8(acc, v0); acc8(acc, v1); acc8(acc, v2); acc8(acc, v3);
    }
    for (; j < d; j++) {
        int s = g_col[start + j];
        uint4 v = *(const uint4*)(h + s * HD + l16 * 8);
        acc8(acc, v);
    }
    float inv = 1.f / (float)max(d, 1);
    uint4 w;
    w.x = pack2h(acc[0] * inv, acc[1] * inv);
    w.y = pack2h(acc[2] * inv, acc[3] * inv);
    w.z = pack2h(acc[4] * inv, acc[5] * inv);
    w.w = pack2h(acc[6] * inv, acc[7] * inv);
    g_agg4[node * 16 + l16] = w;
}

// ---------------- fp16 tensor-core GEMM + bias + LayerNorm + ReLU ----------------
// Block 128x128, 8 warps as 4x2 (warptile 32x64). K=256 logical:
//   kc 0..3: A = g_agg4 (fp16 hi), kc 4..7: A = g_h (fp16 exact)
//   B = Wl/Wr packed hi/lo. 2 uniform mma terms: Ah*Bh + Ah*Bl.
// All global ops 16B; all A smem stores STS.128, conflict-free.
#define KPW 20   // uint32 words per row per 32-k chunk (padded)

__global__ void __launch_bounds__(256) gemm_fused_f16(
    int ibuf, int layer,
    const float* __restrict__ bias, const float* __restrict__ gamma,
    const float* __restrict__ beta,
    int obuf, float* __restrict__ ext_out) {
    __shared__ uint32_t As_hi[128 * KPW];
    __shared__ uint32_t Bs_hi[128 * KPW], Bs_lo[128 * KPW];
    __shared__ float bias_s[128], gamma_s[128], beta_s[128];
    __shared__ float red[128 * 4];

    __half* __restrict__ out_h = g_h[obuf];
    const __half* __restrict__ Hp = g_h[ibuf];
    const uint4* __restrict__ Wsp = g_Wsplit + layer * 2 * HD * 32;

    int tid = threadIdx.x;
    int lane = tid & 31;
    int warp = tid >> 5;
    int g = lane >> 2;
    int t = lane & 3;
    int wrow = (warp >> 1) * 32;
    int wcol = (warp & 1) * 64;
    int brow = blockIdx.x * 128;

    if (tid < 128) {
        bias_s[tid] = bias[tid];
        gamma_s[tid] = gamma[tid];
        beta_s[tid] = beta[tid];
    }

    // A staging map: 2 iters, row = (tid&63)+it*64, quad sq = tid>>6 (8 k each)
    int srow = tid & 63;
    int sq = tid >> 6;
    // B staging map: 4 iters, row = (tid>>3)+it*32, group akq = tid&7 (4 k each)
    int arow = tid >> 3, akq = tid & 7;

    float acc[2][8][4];
#pragma unroll
    for (int mi = 0; mi < 2; mi++)
#pragma unroll
        for (int ni = 0; ni < 8; ni++)
#pragma unroll
            for (int c = 0; c < 4; c++) acc[mi][ni][c] = 0.f;

    uint4 pa[2];    // A (both halves: 8 k of fp16 per uint4)
    uint4 pbw[4];   // packed weights hi/lo

    // ---- prefetch chunk 0 (agg + Wl) ----
#pragma unroll
    for (int it = 0; it < 2; it++) {
        int grow = brow + srow + it * 64;
        pa[it] = (grow < NN) ? g_agg4[grow * 16 + sq]
                             : make_uint4(0u, 0u, 0u, 0u);
    }
#pragma unroll
    for (int it = 0; it < 4; it++)
        pbw[it] = Wsp[(arow + it * 32) * 32 + akq];

    for (int kc = 0; kc < 8; kc++) {
        if (kc > 0) __syncthreads();
        // ---- store prefetched regs -> smem (STS.128 for A) ----
#pragma unroll
        for (int it = 0; it < 2; it++) {
            int row = srow + it * 64;
            *(uint4*)&As_hi[row * KPW + sq * 4] = pa[it];
        }
#pragma unroll
        for (int it = 0; it < 4; it++) {
            int o = (arow + it * 32) * KPW + akq * 2;
            Bs_hi[o]     = pbw[it].x;
            Bs_hi[o + 1] = pbw[it].y;
            Bs_lo[o]     = pbw[it].z;
            Bs_lo[o + 1] = pbw[it].w;
        }
        __syncthreads();
        // ---- prefetch next chunk (LDGs overlap the mma below) ----
        if (kc < 7) {
            int kn = kc + 1;
            bool nagg = (kn < 4);
            if (nagg) {
#pragma unroll
                for (int it = 0; it < 2; it++) {
                    int grow = brow + srow + it * 64;
                    pa[it] = (grow < NN) ? g_agg4[grow * 16 + kn * 4 + sq]
                                         : make_uint4(0u, 0u, 0u, 0u);
                }
            } else {
                int col0 = (kn & 3) * 32;
#pragma unroll
                for (int it = 0; it < 2; it++) {
                    int grow = brow + srow + it * 64;
                    pa[it] = (grow < NN)
                                 ? *(const uint4*)(Hp + grow * HD + col0 + sq * 8)
                                 : make_uint4(0u, 0u, 0u, 0u);
                }
            }
            const uint4* __restrict__ Wp = Wsp + (nagg ? 0 : HD * 32);
            int gq = (kn & 3) * 8 + akq;
#pragma unroll
            for (int it = 0; it < 4; it++)
                pbw[it] = Wp[(arow + it * 32) * 32 + gq];
        }
        // ---- mma on chunk kc: 2 terms (Ah*Bh + Ah*Bl) ----
#pragma unroll
        for (int ks = 0; ks < 2; ks++) {
            int kw = ks * 8;
            uint32_t ah[2][4], bh[8][2], bl[8][2];
#pragma unroll
            for (int mi = 0; mi < 2; mi++) {
                int r0 = (wrow + mi * 16 + g) * KPW + kw;
                ah[mi][0] = As_hi[r0 + t];
                ah[mi][1] = As_hi[r0 + 8 * KPW + t];
                ah[mi][2] = As_hi[r0 + t + 4];
                ah[mi][3] = As_hi[r0 + 8 * KPW + t + 4];
            }
#pragma unroll
            for (int ni = 0; ni < 8; ni++) {
                int c0 = (wcol + ni * 8 + g) * KPW + kw;
                bh[ni][0] = Bs_hi[c0 + t];
                bh[ni][1] = Bs_hi[c0 + t + 4];
                bl[ni][0] = Bs_lo[c0 + t];
                bl[ni][1] = Bs_lo[c0 + t + 4];
            }
#pragma unroll
            for (int mi = 0; mi < 2; mi++)
#pragma unroll
                for (int ni = 0; ni < 8; ni++) {
                    mma_f16(acc[mi][ni], ah[mi][0], ah[mi][1], ah[mi][2], ah[mi][3],
                            bh[ni][0], bh[ni][1]);
                    mma_f16(acc[mi][ni], ah[mi][0], ah[mi][1], ah[mi][2], ah[mi][3],
                            bl[ni][0], bl[ni][1]);
                }
        }
    }
    __syncthreads();

    // ---- epilogue: bias + LN(128 cols) + ReLU ----
    float ps[2][2], pq[2][2];
#pragma unroll
    for (int mi = 0; mi < 2; mi++)
#pragma unroll
        for (int h = 0; h < 2; h++) { ps[mi][h] = 0.f; pq[mi][h] = 0.f; }
#pragma unroll
    for (int mi = 0; mi < 2; mi++)
#pragma unroll
        for (int ni = 0; ni < 8; ni++) {
            int cbase = wcol + ni * 8 + 2 * t;
            float b0v = bias_s[cbase], b1v = bias_s[cbase + 1];
            float v;
            v = acc[mi][ni][0] + b0v; acc[mi][ni][0] = v; ps[mi][0] += v; pq[mi][0] += v * v;
            v = acc[mi][ni][1] + b1v; acc[mi][ni][1] = v; ps[mi][0] += v; pq[mi][0] += v * v;
            v = acc[mi][ni][2] + b0v; acc[mi][ni][2] = v; ps[mi][1] += v; pq[mi][1] += v * v;
            v = acc[mi][ni][3] + b1v; acc[mi][ni][3] = v; ps[mi][1] += v; pq[mi][1] += v * v;
        }
#pragma unroll
    for (int mi = 0; mi < 2; mi++)
#pragma unroll
        for (int h = 0; h < 2; h++) {
#pragma unroll
            for (int o = 1; o < 4; o <<= 1) {
                ps[mi][h] += __shfl_xor_sync(0xffffffffu, ps[mi][h], o);
                pq[mi][h] += __shfl_xor_sync(0xffffffffu, pq[mi][h], o);
            }
        }
    if (t == 0) {
#pragma unroll
        for (int mi = 0; mi < 2; mi++)
#pragma unroll
            for (int h = 0; h < 2; h++) {
                int rl = wrow + mi * 16 + h * 8 + g;
                red[rl * 4 + (warp & 1) * 2 + 0] = ps[mi][h];
                red[rl * 4 + (warp & 1) * 2 + 1] = pq[mi][h];
            }
    }
    __syncthreads();
#pragma unroll
    for (int mi = 0; mi < 2; mi++)
#pragma unroll
        for (int h = 0; h < 2; h++) {
            int rl = wrow + mi * 16 + h * 8 + g;
            float S = red[rl * 4 + 0] + red[rl * 4 + 2];
            float Q = red[rl * 4 + 1] + red[rl * 4 + 3];
            float mean = S * (1.f / HD);
            float var = Q * (1.f / HD) - mean * mean;
            float rstd = rsqrtf(var + EPS);
            int grow = brow + rl;
            if (grow < NN) {
#pragma unroll
                for (int ni = 0; ni < 8; ni++) {
                    int cbase = wcol + ni * 8 + 2 * t;
                    float v0 = acc[mi][ni][h * 2 + 0];
                    float v1 = acc[mi][ni][h * 2 + 1];
                    float o0 = fmaxf((v0 - mean) * rstd * gamma_s[cbase] + beta_s[cbase], 0.f);
                    float o1 = fmaxf((v1 - mean) * rstd * gamma_s[cbase + 1] + beta_s[cbase + 1], 0.f);
                    // fp16 copy always (layer 3: feeds fp16 pooling)
                    *(uint32_t*)(out_h + grow * HD + cbase) = pack2h(o0, o1);
                    if (ext_out)
                        *(float2*)(ext_out + grow * HD + cbase) = make_float2(o0, o1);
                }
            }
        }
}

// ---------------- pooling (reads fp16 copy of node_embed) ----------------
__global__ void pool_accum(const int* __restrict__ batch, float* __restrict__ gout) {
    int tx = threadIdx.x;  // 128 = column
    int n0 = blockIdx.x * 128;
    int n1 = min(n0 + 128, NN);
    if (n0 >= NN) return;
    const __half* __restrict__ ne = g_h[1];
    int cur = batch[n0];
    float sum = 0.f, mx = 0.f;
    for (int n = n0; n < n1; n++) {
        int b = batch[n];
        float v = __half2float(ne[n * HD + tx]);
        if (b != cur) {
            atomicAdd(&gout[cur * 256 + tx], sum);
            atomicMax((int*)&gout[cur * 256 + HD + tx], __float_as_int(mx));
            sum = 0.f; mx = 0.f; cur = b;
        }
        sum += v;
        mx = fmaxf(mx, v);
    }
    atomicAdd(&gout[cur * 256 + tx], sum);
    atomicMax((int*)&gout[cur * 256 + HD + tx], __float_as_int(mx));
}
__global__ void finalize_pool(float* __restrict__ gout) {
    int b = blockIdx.x;
    int tx = threadIdx.x;
    gout[b * 256 + tx] /= fmaxf(g_cnt[b], 1.f);
}

// ---------------- launch ----------------
extern "C" void kernel_launch(void* const* d_in, const int* in_sizes, int n_in,
                              void* d_out, int out_size) {
    const float* x   = (const float*)d_in[0];
    const int* ei    = (const int*)d_in[1];
    const int* batch = (const int*)d_in[2];
    const float* W0  = (const float*)d_in[3];
    const float* b0  = (const float*)d_in[4];
    const float* g0  = (const float*)d_in[5];
    const float* be0 = (const float*)d_in[6];
    const float* Wl1 = (const float*)d_in[7];
    const float* bl1 = (const float*)d_in[8];
    const float* Wr1 = (const float*)d_in[9];
    const float* g1  = (const float*)d_in[10];
    const float* be1 = (const float*)d_in[11];
    const float* Wl2 = (const float*)d_in[12];
    const float* bl2 = (const float*)d_in[13];
    const float* Wr2 = (const float*)d_in[14];
    const float* g2  = (const float*)d_in[15];
    const float* be2 = (const float*)d_in[16];
    const float* Wl3 = (const float*)d_in[17];
    const float* bl3 = (const float*)d_in[18];
    const float* Wr3 = (const float*)d_in[19];
    const float* g3  = (const float*)d_in[20];
    const float* be3 = (const float*)d_in[21];

    float* out = (float*)d_out;
    float* ne = out;                           // node_embed (N*H)
    float* gr = out + (size_t)NN * HD;         // graph_embed (B*2H)

    const int* src = ei;
    const int* dst = ei + EE;

    prep<<<SW_BLOCKS + NB_SCAN, 256>>>(Wl1, Wr1, Wl2, Wr2, Wl3, Wr3, gr);
    fat_start<<<EMB_BLOCKS + CD_BLOCKS + NB_SCAN, 256>>>(x, W0, b0, g0, be0, dst, batch);
    scan1<<<NB_SCAN, 256>>>();
    scan3<<<NB_SCAN, 256>>>();
    fill_csr<<<(EE + 255) / 256, 256>>>(src, dst);

    int gemm_blocks = (NN + 127) / 128;
    int agg_blocks = (NN / 2 * 32 + 255) / 256;

    // layer 1: h0 -> h1
    aggregate<<<agg_blocks, 256>>>(0);
    gemm_fused_f16<<<gemm_blocks, 256>>>(0, 0, bl1, g1, be1, 1, nullptr);
    // layer 2: h1 -> h0
    aggregate<<<agg_blocks, 256>>>(1);
    gemm_fused_f16<<<gemm_blocks, 256>>>(1, 1, bl2, g2, be2, 0, nullptr);
    // layer 3: h0 -> d_out (fp32) + g_h[1] (fp16, for pooling)
    aggregate<<<agg_blocks, 256>>>(0);
    gemm_fused_f16<<<gemm_blocks, 256>>>(0, 2, bl3, g3, be3, 1, ne);

    pool_accum<<<(NN + 127) / 128, 128>>>(batch, gr);
    finalize_pool<<<BG, 128>>>(gr);
}

// round 14
// speedup vs baseline: 1.5921x; 1.1241x over previous
#include <cuda_runtime.h>
#include <cuda_fp16.h>
#include <cstdint>

#define NN 100000
#define EE 1600000
#define BG 64
#define HD 128
#define DIN 9
#define EPS 1e-5f
#define NB_SCAN 391      // ceil(NN/256)
#define EMB_BLOCKS 3125  // 32 nodes per block
#define CD_BLOCKS 6250   // count_deg blocks
#define SW_BLOCKS 48     // weight convert: 3*2*128*16 / 256

// ---------------- scratch (static __device__, no allocation) ----------------
__device__ __half g_h[2][NN * HD];        // ping-pong node features (fp16)
__device__ uint4  g_agg4[NN * 16];        // agg mean fp16, uint4 per 8 k
__device__ uint4  g_Wh[3 * 2 * HD * 16];  // fp16 weights [layer][part][c][kgroup8]
__device__ int    g_deg[NN];
__device__ int    g_rowptr[NN];
__device__ int    g_cursor[NN];
__device__ int    g_col[EE];
__device__ int    g_bsum[512];
__device__ float  g_cnt[BG];

// ---------------- fp16 helpers ----------------
__device__ __forceinline__ uint32_t pack2h(float a, float b) {
    __half2 t = __floats2half2_rn(a, b);
    return *(uint32_t*)&t;
}
__device__ __forceinline__ void mma_f16(float* c, uint32_t a0, uint32_t a1,
                                        uint32_t a2, uint32_t a3,
                                        uint32_t b0, uint32_t b1) {
    asm volatile(
        "mma.sync.aligned.m16n8k16.row.col.f32.f16.f16.f32 "
        "{%0,%1,%2,%3},{%4,%5,%6,%7},{%8,%9},{%0,%1,%2,%3};\n"
        : "+f"(c[0]), "+f"(c[1]), "+f"(c[2]), "+f"(c[3])
        : "r"(a0), "r"(a1), "r"(a2), "r"(a3), "r"(b0), "r"(b1));
}

// ---------------- prep: weight fp16 convert || zero (deg, cnt, pool out) --------
__global__ void __launch_bounds__(256) prep(
    const float* __restrict__ Wl1, const float* __restrict__ Wr1,
    const float* __restrict__ Wl2, const float* __restrict__ Wr2,
    const float* __restrict__ Wl3, const float* __restrict__ Wr3,
    float* __restrict__ gr) {
    int bid = blockIdx.x;
    if (bid < SW_BLOCKS) {
        int idx = bid * 256 + threadIdx.x;     // 8-float group, 0 .. 12287
        int l = idx >> 12;                     // 4096 groups per layer
        int rem = idx & 4095;                  // part*2048 + c*16 + gq
        int part = rem >> 11;
        int cg = rem & 2047;
        const float* W;
        if (l == 0) W = part ? Wr1 : Wl1;
        else if (l == 1) W = part ? Wr2 : Wl2;
        else W = part ? Wr3 : Wl3;
        float4 a = *(const float4*)(W + cg * 8);
        float4 b = *(const float4*)(W + cg * 8 + 4);
        uint4 w;
        w.x = pack2h(a.x, a.y);
        w.y = pack2h(a.z, a.w);
        w.z = pack2h(b.x, b.y);
        w.w = pack2h(b.z, b.w);
        g_Wh[idx] = w;
    } else {
        int i = (bid - SW_BLOCKS) * 256 + threadIdx.x;
        if (i < NN) g_deg[i] = 0;
        if (i < BG * 2 * HD) gr[i] = 0.f;
        if (i < BG) g_cnt[i] = 0.f;
    }
}

// ---------------- fat start: embed || count_deg || count_batch ----------------
__global__ void __launch_bounds__(256) fat_start(
    const float* __restrict__ x, const float* __restrict__ W0,
    const float* __restrict__ b0, const float* __restrict__ g0,
    const float* __restrict__ be0,
    const int* __restrict__ dst, const int* __restrict__ batch) {
    int bid = blockIdx.x;
    int tid = threadIdx.x;
    if (bid < EMB_BLOCKS) {
        __shared__ float Ws[HD * DIN];
        __shared__ float bs[HD], gs[HD], es[HD];
        for (int i = tid; i < HD * DIN; i += 256) Ws[i] = W0[i];
        if (tid < HD) { bs[tid] = b0[tid]; gs[tid] = g0[tid]; es[tid] = be0[tid]; }
        __syncthreads();
        int warp = tid >> 5;
        int lane = tid & 31;
        __half* hout = g_h[0];
#pragma unroll
        for (int it = 0; it < 4; it++) {
            int n = bid * 32 + it * 8 + warp;   // always < NN (3125*32 == NN)
            float xv = (lane < DIN) ? x[n * DIN + lane] : 0.f;
            float xj[DIN];
#pragma unroll
            for (int j = 0; j < DIN; j++) xj[j] = __shfl_sync(0xffffffffu, xv, j);
            float val[4];
#pragma unroll
            for (int q = 0; q < 4; q++) {
                int f = lane * 4 + q;
                float v = bs[f];
#pragma unroll
                for (int j = 0; j < DIN; j++) v += xj[j] * Ws[f * DIN + j];
                val[q] = v;
            }
            float s = val[0] + val[1] + val[2] + val[3];
            float s2 = val[0]*val[0] + val[1]*val[1] + val[2]*val[2] + val[3]*val[3];
#pragma unroll
            for (int o = 16; o; o >>= 1) {
                s += __shfl_xor_sync(0xffffffffu, s, o);
                s2 += __shfl_xor_sync(0xffffffffu, s2, o);
            }
            float mean = s * (1.f / HD);
            float var = s2 * (1.f / HD) - mean * mean;
            float rstd = rsqrtf(var + EPS);
            uint2 w;
            {
                int f = lane * 4;
                float o0 = fmaxf((val[0] - mean) * rstd * gs[f] + es[f], 0.f);
                float o1 = fmaxf((val[1] - mean) * rstd * gs[f+1] + es[f+1], 0.f);
                float o2 = fmaxf((val[2] - mean) * rstd * gs[f+2] + es[f+2], 0.f);
                float o3 = fmaxf((val[3] - mean) * rstd * gs[f+3] + es[f+3], 0.f);
                w.x = pack2h(o0, o1);
                w.y = pack2h(o2, o3);
            }
            *(uint2*)(hout + n * HD + lane * 4) = w;
        }
    } else if (bid < EMB_BLOCKS + CD_BLOCKS) {
        int e = (bid - EMB_BLOCKS) * 256 + tid;
        if (e < EE) atomicAdd(&g_deg[dst[e]], 1);
    } else {
        int i = (bid - EMB_BLOCKS - CD_BLOCKS) * 256 + tid;
        if (i < NN) atomicAdd(&g_cnt[batch[i]], 1.f);
    }
}

// ---------------- CSR scans + fill ----------------
__global__ void scan1() {
    __shared__ int sm[256];
    int t = threadIdx.x;
    int i = blockIdx.x * 256 + t;
    sm[t] = (i < NN) ? g_deg[i] : 0;
    __syncthreads();
#pragma unroll
    for (int o = 128; o; o >>= 1) {
        if (t < o) sm[t] += sm[t + o];
        __syncthreads();
    }
    if (t == 0) g_bsum[blockIdx.x] = sm[0];
}
// scan3 computes its own block offset by reducing g_bsum[0..bid-1]
__global__ void scan3() {
    __shared__ int sm[256];
    __shared__ int offsh;
    int t = threadIdx.x;
    int partial = 0;
    for (int i = t; i < blockIdx.x; i += 256) partial += g_bsum[i];
#pragma unroll
    for (int o = 16; o; o >>= 1) partial += __shfl_xor_sync(0xffffffffu, partial, o);
    if ((t & 31) == 0) sm[t >> 5] = partial;
    __syncthreads();
    if (t == 0) {
        int s = 0;
#pragma unroll
        for (int w = 0; w < 8; w++) s += sm[w];
        offsh = s;
    }
    __syncthreads();
    int boff = offsh;
    __syncthreads();
    int i = blockIdx.x * 256 + t;
    int v = (i < NN) ? g_deg[i] : 0;
    sm[t] = v;
    __syncthreads();
    for (int o = 1; o < 256; o <<= 1) {
        int add = (t >= o) ? sm[t - o] : 0;
        __syncthreads();
        sm[t] += add;
        __syncthreads();
    }
    if (i < NN) {
        int excl = sm[t] - v + boff;
        g_rowptr[i] = excl;
        g_cursor[i] = excl;
    }
}
__global__ void fill_csr(const int* __restrict__ src, const int* __restrict__ dst) {
    int e = blockIdx.x * blockDim.x + threadIdx.x;
    if (e < EE) {
        int p = atomicAdd(&g_cursor[dst[e]], 1);
        g_col[p] = src[e];
    }
}

// ---------------- mean aggregation: 2 nodes/warp, fp16 output ----------------
__device__ __forceinline__ void acc8(float* acc, uint4 v) {
    float2 t;
    t = __half22float2(*(__half2*)&v.x); acc[0] += t.x; acc[1] += t.y;
    t = __half22float2(*(__half2*)&v.y); acc[2] += t.x; acc[3] += t.y;
    t = __half22float2(*(__half2*)&v.z); acc[4] += t.x; acc[5] += t.y;
    t = __half22float2(*(__half2*)&v.w); acc[6] += t.x; acc[7] += t.y;
}
__global__ void __launch_bounds__(256) aggregate(int ibuf) {
    int gwarp = (blockIdx.x * 256 + threadIdx.x) >> 5;
    int lane = threadIdx.x & 31;
    int node = gwarp * 2 + (lane >> 4);
    int l16 = lane & 15;
    if (node >= NN) return;
    const __half* __restrict__ h = g_h[ibuf];
    int start = g_rowptr[node];
    int d = g_deg[node];
    float acc[8] = {0.f, 0.f, 0.f, 0.f, 0.f, 0.f, 0.f, 0.f};
    int j = 0;
    for (; j + 3 < d; j += 4) {
        int s0 = g_col[start + j];
        int s1 = g_col[start + j + 1];
        int s2 = g_col[start + j + 2];
        int s3 = g_col[start + j + 3];
        uint4 v0 = *(const uint4*)(h + s0 * HD + l16 * 8);
        uint4 v1 = *(const uint4*)(h + s1 * HD + l16 * 8);
        uint4 v2 = *(const uint4*)(h + s2 * HD + l16 * 8);
        uint4 v3 = *(const uint4*)(h + s3 * HD + l16 * 8);
        acc8(acc, v0); acc8(acc, v1); acc8(acc, v2); acc8(acc, v3);
    }
    for (; j < d; j++) {
        int s = g_col[start + j];
        uint4 v = *(const uint4*)(h + s * HD + l16 * 8);
        acc8(acc, v);
    }
    float inv = 1.f / (float)max(d, 1);
    uint4 w;
    w.x = pack2h(acc[0] * inv, acc[1] * inv);
    w.y = pack2h(acc[2] * inv, acc[3] * inv);
    w.z = pack2h(acc[4] * inv, acc[5] * inv);
    w.w = pack2h(acc[6] * inv, acc[7] * inv);
    g_agg4[node * 16 + l16] = w;
}

// ---------------- pure fp16 tensor-core GEMM + bias + LayerNorm + ReLU ------------
// Block 128x128, 8 warps as 4x2 (warptile 32x64). K=256 logical:
//   kc 0..3: A = g_agg4, B = Wl;  kc 4..7: A = g_h, B = Wr.  1 mma term.
// All global ops 16B; all smem stores STS.128, conflict-free (stride 20 words).
#define KPW 20   // uint32 words per row per 32-k chunk (padded)

__global__ void __launch_bounds__(256) gemm_fused_f16(
    int ibuf, int layer,
    const float* __restrict__ bias, const float* __restrict__ gamma,
    const float* __restrict__ beta,
    int obuf, float* __restrict__ ext_out) {
    __shared__ uint32_t As[128 * KPW];
    __shared__ uint32_t Bs[128 * KPW];
    __shared__ float bias_s[128], gamma_s[128], beta_s[128];
    __shared__ float red[128 * 4];

    __half* __restrict__ out_h = g_h[obuf];
    const __half* __restrict__ Hp = g_h[ibuf];
    const uint4* __restrict__ Wsp = g_Wh + layer * 2 * HD * 16;

    int tid = threadIdx.x;
    int lane = tid & 31;
    int warp = tid >> 5;
    int g = lane >> 2;
    int t = lane & 3;
    int wrow = (warp >> 1) * 32;
    int wcol = (warp & 1) * 64;
    int brow = blockIdx.x * 128;

    if (tid < 128) {
        bias_s[tid] = bias[tid];
        gamma_s[tid] = gamma[tid];
        beta_s[tid] = beta[tid];
    }

    // staging map (A and B identical): row = (tid&63)+it*64, sq = tid>>6 (8 k each)
    int srow = tid & 63;
    int sq = tid >> 6;

    float acc[2][8][4];
#pragma unroll
    for (int mi = 0; mi < 2; mi++)
#pragma unroll
        for (int ni = 0; ni < 8; ni++)
#pragma unroll
            for (int c = 0; c < 4; c++) acc[mi][ni][c] = 0.f;

    uint4 pa[2];    // A: 8 k of fp16 per uint4
    uint4 pbw[2];   // B: 8 k of fp16 per uint4

    // ---- prefetch chunk 0 (agg + Wl) ----
#pragma unroll
    for (int it = 0; it < 2; it++) {
        int grow = brow + srow + it * 64;
        pa[it] = (grow < NN) ? g_agg4[grow * 16 + sq]
                             : make_uint4(0u, 0u, 0u, 0u);
        pbw[it] = Wsp[(srow + it * 64) * 16 + sq];
    }

    for (int kc = 0; kc < 8; kc++) {
        if (kc > 0) __syncthreads();
        // ---- store prefetched regs -> smem (STS.128) ----
#pragma unroll
        for (int it = 0; it < 2; it++) {
            int row = srow + it * 64;
            *(uint4*)&As[row * KPW + sq * 4] = pa[it];
            *(uint4*)&Bs[row * KPW + sq * 4] = pbw[it];
        }
        __syncthreads();
        // ---- prefetch next chunk (LDGs overlap the mma below) ----
        if (kc < 7) {
            int kn = kc + 1;
            bool nagg = (kn < 4);
            int gq = (kn & 3) * 4 + sq;
            if (nagg) {
#pragma unroll
                for (int it = 0; it < 2; it++) {
                    int grow = brow + srow + it * 64;
                    pa[it] = (grow < NN) ? g_agg4[grow * 16 + gq]
                                         : make_uint4(0u, 0u, 0u, 0u);
                }
            } else {
                int col0 = (kn & 3) * 32;
#pragma unroll
                for (int it = 0; it < 2; it++) {
                    int grow = brow + srow + it * 64;
                    pa[it] = (grow < NN)
                                 ? *(const uint4*)(Hp + grow * HD + col0 + sq * 8)
                                 : make_uint4(0u, 0u, 0u, 0u);
                }
            }
            const uint4* __restrict__ Wp = Wsp + (nagg ? 0 : HD * 16);
#pragma unroll
            for (int it = 0; it < 2; it++)
                pbw[it] = Wp[(srow + it * 64) * 16 + gq];
        }
        // ---- mma on chunk kc: 1 term ----
#pragma unroll
        for (int ks = 0; ks < 2; ks++) {
            int kw = ks * 8;
            uint32_t ah[2][4], bh[8][2];
#pragma unroll
            for (int mi = 0; mi < 2; mi++) {
                int r0 = (wrow + mi * 16 + g) * KPW + kw;
                ah[mi][0] = As[r0 + t];
                ah[mi][1] = As[r0 + 8 * KPW + t];
                ah[mi][2] = As[r0 + t + 4];
                ah[mi][3] = As[r0 + 8 * KPW + t + 4];
            }
#pragma unroll
            for (int ni = 0; ni < 8; ni++) {
                int c0 = (wcol + ni * 8 + g) * KPW + kw;
                bh[ni][0] = Bs[c0 + t];
                bh[ni][1] = Bs[c0 + t + 4];
            }
#pragma unroll
            for (int mi = 0; mi < 2; mi++)
#pragma unroll
                for (int ni = 0; ni < 8; ni++)
                    mma_f16(acc[mi][ni], ah[mi][0], ah[mi][1], ah[mi][2], ah[mi][3],
                            bh[ni][0], bh[ni][1]);
        }
    }
    __syncthreads();

    // ---- epilogue: bias + LN(128 cols) + ReLU ----
    float ps[2][2], pq[2][2];
#pragma unroll
    for (int mi = 0; mi < 2; mi++)
#pragma unroll
        for (int h = 0; h < 2; h++) { ps[mi][h] = 0.f; pq[mi][h] = 0.f; }
#pragma unroll
    for (int mi = 0; mi < 2; mi++)
#pragma unroll
        for (int ni = 0; ni < 8; ni++) {
            int cbase = wcol + ni * 8 + 2 * t;
            float b0v = bias_s[cbase], b1v = bias_s[cbase + 1];
            float v;
            v = acc[mi][ni][0] + b0v; acc[mi][ni][0] = v; ps[mi][0] += v; pq[mi][0] += v * v;
            v = acc[mi][ni][1] + b1v; acc[mi][ni][1] = v; ps[mi][0] += v; pq[mi][0] += v * v;
            v = acc[mi][ni][2] + b0v; acc[mi][ni][2] = v; ps[mi][1] += v; pq[mi][1] += v * v;
            v = acc[mi][ni][3] + b1v; acc[mi][ni][3] = v; ps[mi][1] += v; pq[mi][1] += v * v;
        }
#pragma unroll
    for (int mi = 0; mi < 2; mi++)
#pragma unroll
        for (int h = 0; h < 2; h++) {
#pragma unroll
            for (int o = 1; o < 4; o <<= 1) {
                ps[mi][h] += __shfl_xor_sync(0xffffffffu, ps[mi][h], o);
                pq[mi][h] += __shfl_xor_sync(0xffffffffu, pq[mi][h], o);
            }
        }
    if (t == 0) {
#pragma unroll
        for (int mi = 0; mi < 2; mi++)
#pragma unroll
            for (int h = 0; h < 2; h++) {
                int rl = wrow + mi * 16 + h * 8 + g;
                red[rl * 4 + (warp & 1) * 2 + 0] = ps[mi][h];
                red[rl * 4 + (warp & 1) * 2 + 1] = pq[mi][h];
            }
    }
    __syncthreads();
#pragma unroll
    for (int mi = 0; mi < 2; mi++)
#pragma unroll
        for (int h = 0; h < 2; h++) {
            int rl = wrow + mi * 16 + h * 8 + g;
            float S = red[rl * 4 + 0] + red[rl * 4 + 2];
            float Q = red[rl * 4 + 1] + red[rl * 4 + 3];
            float mean = S * (1.f / HD);
            float var = Q * (1.f / HD) - mean * mean;
            float rstd = rsqrtf(var + EPS);
            int grow = brow + rl;
            if (grow < NN) {
#pragma unroll
                for (int ni = 0; ni < 8; ni++) {
                    int cbase = wcol + ni * 8 + 2 * t;
                    float v0 = acc[mi][ni][h * 2 + 0];
                    float v1 = acc[mi][ni][h * 2 + 1];
                    float o0 = fmaxf((v0 - mean) * rstd * gamma_s[cbase] + beta_s[cbase], 0.f);
                    float o1 = fmaxf((v1 - mean) * rstd * gamma_s[cbase + 1] + beta_s[cbase + 1], 0.f);
                    // fp16 copy always (layer 3: feeds fp16 pooling)
                    *(uint32_t*)(out_h + grow * HD + cbase) = pack2h(o0, o1);
                    if (ext_out)
                        *(float2*)(ext_out + grow * HD + cbase) = make_float2(o0, o1);
                }
            }
        }
}

// ---------------- pooling (reads fp16 copy of node_embed) ----------------
__global__ void pool_accum(const int* __restrict__ batch, float* __restrict__ gout) {
    int tx = threadIdx.x;  // 128 = column
    int n0 = blockIdx.x * 128;
    int n1 = min(n0 + 128, NN);
    if (n0 >= NN) return;
    const __half* __restrict__ ne = g_h[1];
    int cur = batch[n0];
    float sum = 0.f, mx = 0.f;
    for (int n = n0; n < n1; n++) {
        int b = batch[n];
        float v = __half2float(ne[n * HD + tx]);
        if (b != cur) {
            atomicAdd(&gout[cur * 256 + tx], sum);
            atomicMax((int*)&gout[cur * 256 + HD + tx], __float_as_int(mx));
            sum = 0.f; mx = 0.f; cur = b;
        }
        sum += v;
        mx = fmaxf(mx, v);
    }
    atomicAdd(&gout[cur * 256 + tx], sum);
    atomicMax((int*)&gout[cur * 256 + HD + tx], __float_as_int(mx));
}
__global__ void finalize_pool(float* __restrict__ gout) {
    int b = blockIdx.x;
    int tx = threadIdx.x;
    gout[b * 256 + tx] /= fmaxf(g_cnt[b], 1.f);
}

// ---------------- launch ----------------
extern "C" void kernel_launch(void* const* d_in, const int* in_sizes, int n_in,
                              void* d_out, int out_size) {
    const float* x   = (const float*)d_in[0];
    const int* ei    = (const int*)d_in[1];
    const int* batch = (const int*)d_in[2];
    const float* W0  = (const float*)d_in[3];
    const float* b0  = (const float*)d_in[4];
    const float* g0  = (const float*)d_in[5];
    const float* be0 = (const float*)d_in[6];
    const float* Wl1 = (const float*)d_in[7];
    const float* bl1 = (const float*)d_in[8];
    const float* Wr1 = (const float*)d_in[9];
    const float* g1  = (const float*)d_in[10];
    const float* be1 = (const float*)d_in[11];
    const float* Wl2 = (const float*)d_in[12];
    const float* bl2 = (const float*)d_in[13];
    const float* Wr2 = (const float*)d_in[14];
    const float* g2  = (const float*)d_in[15];
    const float* be2 = (const float*)d_in[16];
    const float* Wl3 = (const float*)d_in[17];
    const float* bl3 = (const float*)d_in[18];
    const float* Wr3 = (const float*)d_in[19];
    const float* g3  = (const float*)d_in[20];
    const float* be3 = (const float*)d_in[21];

    float* out = (float*)d_out;
    float* ne = out;                           // node_embed (N*H)
    float* gr = out + (size_t)NN * HD;         // graph_embed (B*2H)

    const int* src = ei;
    const int* dst = ei + EE;

    prep<<<SW_BLOCKS + NB_SCAN, 256>>>(Wl1, Wr1, Wl2, Wr2, Wl3, Wr3, gr);
    fat_start<<<EMB_BLOCKS + CD_BLOCKS + NB_SCAN, 256>>>(x, W0, b0, g0, be0, dst, batch);
    scan1<<<NB_SCAN, 256>>>();
    scan3<<<NB_SCAN, 256>>>();
    fill_csr<<<(EE + 255) / 256, 256>>>(src, dst);

    int gemm_blocks = (NN + 127) / 128;
    int agg_blocks = (NN / 2 * 32 + 255) / 256;

    // layer 1: h0 -> h1
    aggregate<<<agg_blocks, 256>>>(0);
    gemm_fused_f16<<<gemm_blocks, 256>>>(0, 0, bl1, g1, be1, 1, nullptr);
    // layer 2: h1 -> h0
    aggregate<<<agg_blocks, 256>>>(1);
    gemm_fused_f16<<<gemm_blocks, 256>>>(1, 1, bl2, g2, be2, 0, nullptr);
    // layer 3: h0 -> d_out (fp32) + g_h[1] (fp16, for pooling)
    aggregate<<<agg_blocks, 256>>>(0);
    gemm_fused_f16<<<gemm_blocks, 256>>>(0, 2, bl3, g3, be3, 1, ne);

    pool_accum<<<(NN + 127) / 128, 128>>>(batch, gr);
    finalize_pool<<<BG, 128>>>(gr);
}

// round 15
// speedup vs baseline: 1.6094x; 1.0109x over previous
#include <cuda_runtime.h>
#include <cuda_fp16.h>
#include <cstdint>

#define NN 100000
#define EE 1600000
#define BG 64
#define HD 128
#define DIN 9
#define EPS 1e-5f
#define NB_SCAN 391      // ceil(NN/256)
#define EMB_BLOCKS 3125  // 32 nodes per block
#define CD_BLOCKS 6250   // count_deg blocks
#define SW_BLOCKS 48     // weight convert: 3*2*128*16 / 256

// ---------------- scratch (static __device__, no allocation) ----------------
__device__ __half g_h[2][NN * HD];        // ping-pong node features (fp16)
__device__ uint4  g_agg4[NN * 16];        // agg mean fp16, uint4 per 8 k
__device__ uint4  g_Wh[3 * 2 * HD * 16];  // fp16 weights [layer][part][c][kgroup8]
__device__ int    g_deg[NN];
__device__ int    g_rowptr[NN];
__device__ int    g_cursor[NN];
__device__ int    g_col[EE];
__device__ int    g_bsum[512];
__device__ float  g_cnt[BG];

// ---------------- fp16 helpers ----------------
__device__ __forceinline__ uint32_t pack2h(float a, float b) {
    __half2 t = __floats2half2_rn(a, b);
    return *(uint32_t*)&t;
}
__device__ __forceinline__ void mma_f16(float* c, uint32_t a0, uint32_t a1,
                                        uint32_t a2, uint32_t a3,
                                        uint32_t b0, uint32_t b1) {
    asm volatile(
        "mma.sync.aligned.m16n8k16.row.col.f32.f16.f16.f32 "
        "{%0,%1,%2,%3},{%4,%5,%6,%7},{%8,%9},{%0,%1,%2,%3};\n"
        : "+f"(c[0]), "+f"(c[1]), "+f"(c[2]), "+f"(c[3])
        : "r"(a0), "r"(a1), "r"(a2), "r"(a3), "r"(b0), "r"(b1));
}

// ---------------- prep: weight fp16 convert || zero (deg, cnt, pool out) --------
__global__ void __launch_bounds__(256) prep(
    const float* __restrict__ Wl1, const float* __restrict__ Wr1,
    const float* __restrict__ Wl2, const float* __restrict__ Wr2,
    const float* __restrict__ Wl3, const float* __restrict__ Wr3,
    float* __restrict__ gr) {
    int bid = blockIdx.x;
    if (bid < SW_BLOCKS) {
        int idx = bid * 256 + threadIdx.x;     // 8-float group, 0 .. 12287
        int l = idx >> 12;                     // 4096 groups per layer
        int rem = idx & 4095;
        int part = rem >> 11;
        int cg = rem & 2047;
        const float* W;
        if (l == 0) W = part ? Wr1 : Wl1;
        else if (l == 1) W = part ? Wr2 : Wl2;
        else W = part ? Wr3 : Wl3;
        float4 a = *(const float4*)(W + cg * 8);
        float4 b = *(const float4*)(W + cg * 8 + 4);
        uint4 w;
        w.x = pack2h(a.x, a.y);
        w.y = pack2h(a.z, a.w);
        w.z = pack2h(b.x, b.y);
        w.w = pack2h(b.z, b.w);
        g_Wh[idx] = w;
    } else {
        int i = (bid - SW_BLOCKS) * 256 + threadIdx.x;
        if (i < NN) g_deg[i] = 0;
        if (i < BG * 2 * HD) gr[i] = 0.f;
        if (i < BG) g_cnt[i] = 0.f;
    }
}

// ---------------- fat start: embed || count_deg || count_batch ----------------
__global__ void __launch_bounds__(256) fat_start(
    const float* __restrict__ x, const float* __restrict__ W0,
    const float* __restrict__ b0, const float* __restrict__ g0,
    const float* __restrict__ be0,
    const int* __restrict__ dst, const int* __restrict__ batch) {
    int bid = blockIdx.x;
    int tid = threadIdx.x;
    if (bid < EMB_BLOCKS) {
        __shared__ float Ws[HD * DIN];
        __shared__ float bs[HD], gs[HD], es[HD];
        for (int i = tid; i < HD * DIN; i += 256) Ws[i] = W0[i];
        if (tid < HD) { bs[tid] = b0[tid]; gs[tid] = g0[tid]; es[tid] = be0[tid]; }
        __syncthreads();
        int warp = tid >> 5;
        int lane = tid & 31;
        __half* hout = g_h[0];
#pragma unroll
        for (int it = 0; it < 4; it++) {
            int n = bid * 32 + it * 8 + warp;   // always < NN (3125*32 == NN)
            float xv = (lane < DIN) ? x[n * DIN + lane] : 0.f;
            float xj[DIN];
#pragma unroll
            for (int j = 0; j < DIN; j++) xj[j] = __shfl_sync(0xffffffffu, xv, j);
            float val[4];
#pragma unroll
            for (int q = 0; q < 4; q++) {
                int f = lane * 4 + q;
                float v = bs[f];
#pragma unroll
                for (int j = 0; j < DIN; j++) v += xj[j] * Ws[f * DIN + j];
                val[q] = v;
            }
            float s = val[0] + val[1] + val[2] + val[3];
            float s2 = val[0]*val[0] + val[1]*val[1] + val[2]*val[2] + val[3]*val[3];
#pragma unroll
            for (int o = 16; o; o >>= 1) {
                s += __shfl_xor_sync(0xffffffffu, s, o);
                s2 += __shfl_xor_sync(0xffffffffu, s2, o);
            }
            float mean = s * (1.f / HD);
            float var = s2 * (1.f / HD) - mean * mean;
            float rstd = rsqrtf(var + EPS);
            uint2 w;
            {
                int f = lane * 4;
                float o0 = fmaxf((val[0] - mean) * rstd * gs[f] + es[f], 0.f);
                float o1 = fmaxf((val[1] - mean) * rstd * gs[f+1] + es[f+1], 0.f);
                float o2 = fmaxf((val[2] - mean) * rstd * gs[f+2] + es[f+2], 0.f);
                float o3 = fmaxf((val[3] - mean) * rstd * gs[f+3] + es[f+3], 0.f);
                w.x = pack2h(o0, o1);
                w.y = pack2h(o2, o3);
            }
            *(uint2*)(hout + n * HD + lane * 4) = w;
        }
    } else if (bid < EMB_BLOCKS + CD_BLOCKS) {
        int e = (bid - EMB_BLOCKS) * 256 + tid;
        if (e < EE) atomicAdd(&g_deg[dst[e]], 1);
    } else {
        int i = (bid - EMB_BLOCKS - CD_BLOCKS) * 256 + tid;
        if (i < NN) atomicAdd(&g_cnt[batch[i]], 1.f);
    }
}

// ---------------- CSR scans + fill ----------------
__global__ void scan1() {
    __shared__ int sm[256];
    int t = threadIdx.x;
    int i = blockIdx.x * 256 + t;
    sm[t] = (i < NN) ? g_deg[i] : 0;
    __syncthreads();
#pragma unroll
    for (int o = 128; o; o >>= 1) {
        if (t < o) sm[t] += sm[t + o];
        __syncthreads();
    }
    if (t == 0) g_bsum[blockIdx.x] = sm[0];
}
// scan3 computes its own block offset by reducing g_bsum[0..bid-1]
__global__ void scan3() {
    __shared__ int sm[256];
    __shared__ int offsh;
    int t = threadIdx.x;
    int partial = 0;
    for (int i = t; i < blockIdx.x; i += 256) partial += g_bsum[i];
#pragma unroll
    for (int o = 16; o; o >>= 1) partial += __shfl_xor_sync(0xffffffffu, partial, o);
    if ((t & 31) == 0) sm[t >> 5] = partial;
    __syncthreads();
    if (t == 0) {
        int s = 0;
#pragma unroll
        for (int w = 0; w < 8; w++) s += sm[w];
        offsh = s;
    }
    __syncthreads();
    int boff = offsh;
    __syncthreads();
    int i = blockIdx.x * 256 + t;
    int v = (i < NN) ? g_deg[i] : 0;
    sm[t] = v;
    __syncthreads();
    for (int o = 1; o < 256; o <<= 1) {
        int add = (t >= o) ? sm[t - o] : 0;
        __syncthreads();
        sm[t] += add;
        __syncthreads();
    }
    if (i < NN) {
        int excl = sm[t] - v + boff;
        g_rowptr[i] = excl;
        g_cursor[i] = excl;
    }
}
__global__ void fill_csr(const int* __restrict__ src, const int* __restrict__ dst) {
    int e = blockIdx.x * blockDim.x + threadIdx.x;
    if (e < EE) {
        int p = atomicAdd(&g_cursor[dst[e]], 1);
        g_col[p] = src[e];
    }
}

// ---------------- mean aggregation: 2 nodes/warp, 8-deep MLP, fp16 output -------
__device__ __forceinline__ void acc8(float* acc, uint4 v) {
    float2 t;
    t = __half22float2(*(__half2*)&v.x); acc[0] += t.x; acc[1] += t.y;
    t = __half22float2(*(__half2*)&v.y); acc[2] += t.x; acc[3] += t.y;
    t = __half22float2(*(__half2*)&v.z); acc[4] += t.x; acc[5] += t.y;
    t = __half22float2(*(__half2*)&v.w); acc[6] += t.x; acc[7] += t.y;
}
__global__ void __launch_bounds__(256) aggregate(int ibuf) {
    int gwarp = (blockIdx.x * 256 + threadIdx.x) >> 5;
    int lane = threadIdx.x & 31;
    int node = gwarp * 2 + (lane >> 4);
    int l16 = lane & 15;
    if (node >= NN) return;
    const __half* __restrict__ h = g_h[ibuf];
    int start = g_rowptr[node];
    int d = g_deg[node];
    float acc[8] = {0.f, 0.f, 0.f, 0.f, 0.f, 0.f, 0.f, 0.f};
    int j = 0;
    for (; j + 7 < d; j += 8) {
        int s0 = g_col[start + j];
        int s1 = g_col[start + j + 1];
        int s2 = g_col[start + j + 2];
        int s3 = g_col[start + j + 3];
        int s4 = g_col[start + j + 4];
        int s5 = g_col[start + j + 5];
        int s6 = g_col[start + j + 6];
        int s7 = g_col[start + j + 7];
        uint4 v0 = *(const uint4*)(h + s0 * HD + l16 * 8);
        uint4 v1 = *(const uint4*)(h + s1 * HD + l16 * 8);
        uint4 v2 = *(const uint4*)(h + s2 * HD + l16 * 8);
        uint4 v3 = *(const uint4*)(h + s3 * HD + l16 * 8);
        uint4 v4 = *(const uint4*)(h + s4 * HD + l16 * 8);
        uint4 v5 = *(const uint4*)(h + s5 * HD + l16 * 8);
        uint4 v6 = *(const uint4*)(h + s6 * HD + l16 * 8);
        uint4 v7 = *(const uint4*)(h + s7 * HD + l16 * 8);
        acc8(acc, v0); acc8(acc, v1); acc8(acc, v2); acc8(acc, v3);
        acc8(acc, v4); acc8(acc, v5); acc8(acc, v6); acc8(acc, v7);
    }
    if (j + 3 < d) {
        int s0 = g_col[start + j];
        int s1 = g_col[start + j + 1];
        int s2 = g_col[start + j + 2];
        int s3 = g_col[start + j + 3];
        uint4 v0 = *(const uint4*)(h + s0 * HD + l16 * 8);
        uint4 v1 = *(const uint4*)(h + s1 * HD + l16 * 8);
        uint4 v2 = *(const uint4*)(h + s2 * HD + l16 * 8);
        uint4 v3 = *(const uint4*)(h + s3 * HD + l16 * 8);
        acc8(acc, v0); acc8(acc, v1); acc8(acc, v2); acc8(acc, v3);
        j += 4;
    }
    for (; j < d; j++) {
        int s = g_col[start + j];
        uint4 v = *(const uint4*)(h + s * HD + l16 * 8);
        acc8(acc, v);
    }
    float inv = 1.f / (float)max(d, 1);
    uint4 w;
    w.x = pack2h(acc[0] * inv, acc[1] * inv);
    w.y = pack2h(acc[2] * inv, acc[3] * inv);
    w.z = pack2h(acc[4] * inv, acc[5] * inv);
    w.w = pack2h(acc[6] * inv, acc[7] * inv);
    g_agg4[node * 16 + l16] = w;
}

// ---------------- pure fp16 tensor-core GEMM + bias + LayerNorm + ReLU ------------
// Block 128x128, 8 warps as 4x2 (warptile 32x64). K=256 logical:
//   kc 0..3: A = g_agg4, B = Wl;  kc 4..7: A = g_h, B = Wr.  1 mma term.
// Double-buffered smem: store targets the idle buffer -> ONE sync per chunk.
#define KPW 20   // uint32 words per row per 32-k chunk (padded)

__global__ void __launch_bounds__(256) gemm_fused_f16(
    int ibuf, int layer,
    const float* __restrict__ bias, const float* __restrict__ gamma,
    const float* __restrict__ beta,
    int obuf, float* __restrict__ ext_out) {
    __shared__ uint32_t As[2][128 * KPW];
    __shared__ uint32_t Bs[2][128 * KPW];
    __shared__ float bias_s[128], gamma_s[128], beta_s[128];
    __shared__ float red[128 * 4];

    __half* __restrict__ out_h = g_h[obuf];
    const __half* __restrict__ Hp = g_h[ibuf];
    const uint4* __restrict__ Wsp = g_Wh + layer * 2 * HD * 16;

    int tid = threadIdx.x;
    int lane = tid & 31;
    int warp = tid >> 5;
    int g = lane >> 2;
    int t = lane & 3;
    int wrow = (warp >> 1) * 32;
    int wcol = (warp & 1) * 64;
    int brow = blockIdx.x * 128;

    if (tid < 128) {
        bias_s[tid] = bias[tid];
        gamma_s[tid] = gamma[tid];
        beta_s[tid] = beta[tid];
    }

    // staging map (A and B identical): row = (tid&63)+it*64, sq = tid>>6 (8 k each)
    int srow = tid & 63;
    int sq = tid >> 6;

    float acc[2][8][4];
#pragma unroll
    for (int mi = 0; mi < 2; mi++)
#pragma unroll
        for (int ni = 0; ni < 8; ni++)
#pragma unroll
            for (int c = 0; c < 4; c++) acc[mi][ni][c] = 0.f;

    uint4 pa[2];    // A: 8 k of fp16 per uint4
    uint4 pbw[2];   // B: 8 k of fp16 per uint4

    // ---- prefetch chunk 0 (agg + Wl) and store to buffer 0 ----
#pragma unroll
    for (int it = 0; it < 2; it++) {
        int grow = brow + srow + it * 64;
        pa[it] = (grow < NN) ? g_agg4[grow * 16 + sq]
                             : make_uint4(0u, 0u, 0u, 0u);
        pbw[it] = Wsp[(srow + it * 64) * 16 + sq];
    }
#pragma unroll
    for (int it = 0; it < 2; it++) {
        int row = srow + it * 64;
        *(uint4*)&As[0][row * KPW + sq * 4] = pa[it];
        *(uint4*)&Bs[0][row * KPW + sq * 4] = pbw[it];
    }
    __syncthreads();

    for (int kc = 0; kc < 8; kc++) {
        int buf = kc & 1;
        // ---- prefetch next chunk (LDGs overlap the mma below) ----
        if (kc < 7) {
            int kn = kc + 1;
            bool nagg = (kn < 4);
            int gq = (kn & 3) * 4 + sq;
            if (nagg) {
#pragma unroll
                for (int it = 0; it < 2; it++) {
                    int grow = brow + srow + it * 64;
                    pa[it] = (grow < NN) ? g_agg4[grow * 16 + gq]
                                         : make_uint4(0u, 0u, 0u, 0u);
                }
            } else {
                int col0 = (kn & 3) * 32;
#pragma unroll
                for (int it = 0; it < 2; it++) {
                    int grow = brow + srow + it * 64;
                    pa[it] = (grow < NN)
                                 ? *(const uint4*)(Hp + grow * HD + col0 + sq * 8)
                                 : make_uint4(0u, 0u, 0u, 0u);
                }
            }
            const uint4* __restrict__ Wp = Wsp + (nagg ? 0 : HD * 16);
#pragma unroll
            for (int it = 0; it < 2; it++)
                pbw[it] = Wp[(srow + it * 64) * 16 + gq];
        }
        // ---- mma on chunk kc (buffer buf) ----
#pragma unroll
        for (int ks = 0; ks < 2; ks++) {
            int kw = ks * 8;
            uint32_t ah[2][4], bh[8][2];
#pragma unroll
            for (int mi = 0; mi < 2; mi++) {
                int r0 = (wrow + mi * 16 + g) * KPW + kw;
                ah[mi][0] = As[buf][r0 + t];
                ah[mi][1] = As[buf][r0 + 8 * KPW + t];
                ah[mi][2] = As[buf][r0 + t + 4];
                ah[mi][3] = As[buf][r0 + 8 * KPW + t + 4];
            }
#pragma unroll
            for (int ni = 0; ni < 8; ni++) {
                int c0 = (wcol + ni * 8 + g) * KPW + kw;
                bh[ni][0] = Bs[buf][c0 + t];
                bh[ni][1] = Bs[buf][c0 + t + 4];
            }
#pragma unroll
            for (int mi = 0; mi < 2; mi++)
#pragma unroll
                for (int ni = 0; ni < 8; ni++)
                    mma_f16(acc[mi][ni], ah[mi][0], ah[mi][1], ah[mi][2], ah[mi][3],
                            bh[ni][0], bh[ni][1]);
        }
        // ---- store prefetched regs into the idle buffer, one sync ----
        if (kc < 7) {
            int nbuf = buf ^ 1;
#pragma unroll
            for (int it = 0; it < 2; it++) {
                int row = srow + it * 64;
                *(uint4*)&As[nbuf][row * KPW + sq * 4] = pa[it];
                *(uint4*)&Bs[nbuf][row * KPW + sq * 4] = pbw[it];
            }
            __syncthreads();
        }
    }
    __syncthreads();

    // ---- epilogue: bias + LN(128 cols) + ReLU ----
    float ps[2][2], pq[2][2];
#pragma unroll
    for (int mi = 0; mi < 2; mi++)
#pragma unroll
        for (int h = 0; h < 2; h++) { ps[mi][h] = 0.f; pq[mi][h] = 0.f; }
#pragma unroll
    for (int mi = 0; mi < 2; mi++)
#pragma unroll
        for (int ni = 0; ni < 8; ni++) {
            int cbase = wcol + ni * 8 + 2 * t;
            float b0v = bias_s[cbase], b1v = bias_s[cbase + 1];
            float v;
            v = acc[mi][ni][0] + b0v; acc[mi][ni][0] = v; ps[mi][0] += v; pq[mi][0] += v * v;
            v = acc[mi][ni][1] + b1v; acc[mi][ni][1] = v; ps[mi][0] += v; pq[mi][0] += v * v;
            v = acc[mi][ni][2] + b0v; acc[mi][ni][2] = v; ps[mi][1] += v; pq[mi][1] += v * v;
            v = acc[mi][ni][3] + b1v; acc[mi][ni][3] = v; ps[mi][1] += v; pq[mi][1] += v * v;
        }
#pragma unroll
    for (int mi = 0; mi < 2; mi++)
#pragma unroll
        for (int h = 0; h < 2; h++) {
#pragma unroll
            for (int o = 1; o < 4; o <<= 1) {
                ps[mi][h] += __shfl_xor_sync(0xffffffffu, ps[mi][h], o);
                pq[mi][h] += __shfl_xor_sync(0xffffffffu, pq[mi][h], o);
            }
        }
    if (t == 0) {
#pragma unroll
        for (int mi = 0; mi < 2; mi++)
#pragma unroll
            for (int h = 0; h < 2; h++) {
                int rl = wrow + mi * 16 + h * 8 + g;
                red[rl * 4 + (warp & 1) * 2 + 0] = ps[mi][h];
                red[rl * 4 + (warp & 1) * 2 + 1] = pq[mi][h];
            }
    }
    __syncthreads();
#pragma unroll
    for (int mi = 0; mi < 2; mi++)
#pragma unroll
        for (int h = 0; h < 2; h++) {
            int rl = wrow + mi * 16 + h * 8 + g;
            float S = red[rl * 4 + 0] + red[rl * 4 + 2];
            float Q = red[rl * 4 + 1] + red[rl * 4 + 3];
            float mean = S * (1.f / HD);
            float var = Q * (1.f / HD) - mean * mean;
            float rstd = rsqrtf(var + EPS);
            int grow = brow + rl;
            if (grow < NN) {
#pragma unroll
                for (int ni = 0; ni < 8; ni++) {
                    int cbase = wcol + ni * 8 + 2 * t;
                    float v0 = acc[mi][ni][h * 2 + 0];
                    float v1 = acc[mi][ni][h * 2 + 1];
                    float o0 = fmaxf((v0 - mean) * rstd * gamma_s[cbase] + beta_s[cbase], 0.f);
                    float o1 = fmaxf((v1 - mean) * rstd * gamma_s[cbase + 1] + beta_s[cbase + 1], 0.f);
                    // fp16 copy always (layer 3: feeds fp16 pooling)
                    *(uint32_t*)(out_h + grow * HD + cbase) = pack2h(o0, o1);
                    if (ext_out)
                        *(float2*)(ext_out + grow * HD + cbase) = make_float2(o0, o1);
                }
            }
        }
}

// ---------------- pooling (reads fp16 copy of node_embed) ----------------
__global__ void pool_accum(const int* __restrict__ batch, float* __restrict__ gout) {
    int tx = threadIdx.x;  // 128 = column
    int n0 = blockIdx.x * 128;
    int n1 = min(n0 + 128, NN);
    if (n0 >= NN) return;
    const __half* __restrict__ ne = g_h[1];
    int cur = batch[n0];
    float sum = 0.f, mx = 0.f;
    for (int n = n0; n < n1; n++) {
        int b = batch[n];
        float v = __half2float(ne[n * HD + tx]);
        if (b != cur) {
            atomicAdd(&gout[cur * 256 + tx], sum);
            atomicMax((int*)&gout[cur * 256 + HD + tx], __float_as_int(mx));
            sum = 0.f; mx = 0.f; cur = b;
        }
        sum += v;
        mx = fmaxf(mx, v);
    }
    atomicAdd(&gout[cur * 256 + tx], sum);
    atomicMax((int*)&gout[cur * 256 + HD + tx], __float_as_int(mx));
}
__global__ void finalize_pool(float* __restrict__ gout) {
    int b = blockIdx.x;
    int tx = threadIdx.x;
    gout[b * 256 + tx] /= fmaxf(g_cnt[b], 1.f);
}

// ---------------- launch ----------------
extern "C" void kernel_launch(void* const* d_in, const int* in_sizes, int n_in,
                              void* d_out, int out_size) {
    const float* x   = (const float*)d_in[0];
    const int* ei    = (const int*)d_in[1];
    const int* batch = (const int*)d_in[2];
    const float* W0  = (const float*)d_in[3];
    const float* b0  = (const float*)d_in[4];
    const float* g0  = (const float*)d_in[5];
    const float* be0 = (const float*)d_in[6];
    const float* Wl1 = (const float*)d_in[7];
    const float* bl1 = (const float*)d_in[8];
    const float* Wr1 = (const float*)d_in[9];
    const float* g1  = (const float*)d_in[10];
    const float* be1 = (const float*)d_in[11];
    const float* Wl2 = (const float*)d_in[12];
    const float* bl2 = (const float*)d_in[13];
    const float* Wr2 = (const float*)d_in[14];
    const float* g2  = (const float*)d_in[15];
    const float* be2 = (const float*)d_in[16];
    const float* Wl3 = (const float*)d_in[17];
    const float* bl3 = (const float*)d_in[18];
    const float* Wr3 = (const float*)d_in[19];
    const float* g3  = (const float*)d_in[20];
    const float* be3 = (const float*)d_in[21];

    float* out = (float*)d_out;
    float* ne = out;                           // node_embed (N*H)
    float* gr = out + (size_t)NN * HD;         // graph_embed (B*2H)

    const int* src = ei;
    const int* dst = ei + EE;

    prep<<<SW_BLOCKS + NB_SCAN, 256>>>(Wl1, Wr1, Wl2, Wr2, Wl3, Wr3, gr);
    fat_start<<<EMB_BLOCKS + CD_BLOCKS + NB_SCAN, 256>>>(x, W0, b0, g0, be0, dst, batch);
    scan1<<<NB_SCAN, 256>>>();
    scan3<<<NB_SCAN, 256>>>();
    fill_csr<<<(EE + 255) / 256, 256>>>(src, dst);

    int gemm_blocks = (NN + 127) / 128;
    int agg_blocks = (NN / 2 * 32 + 255) / 256;

    // layer 1: h0 -> h1
    aggregate<<<agg_blocks, 256>>>(0);
    gemm_fused_f16<<<gemm_blocks, 256>>>(0, 0, bl1, g1, be1, 1, nullptr);
    // layer 2: h1 -> h0
    aggregate<<<agg_blocks, 256>>>(1);
    gemm_fused_f16<<<gemm_blocks, 256>>>(1, 1, bl2, g2, be2, 0, nullptr);
    // layer 3: h0 -> d_out (fp32) + g_h[1] (fp16, for pooling)
    aggregate<<<agg_blocks, 256>>>(0);
    gemm_fused_f16<<<gemm_blocks, 256>>>(0, 2, bl3, g3, be3, 1, ne);

    pool_accum<<<(NN + 127) / 128, 128>>>(batch, gr);
    finalize_pool<<<BG, 128>>>(gr);
}